// round 1
// baseline (speedup 1.0000x reference)
#include <cuda_runtime.h>
#include <math.h>

#define NMAX 100000
#define EMAX 1000000

// ---------------- scratch (static device globals; no runtime allocation) ----------------
__device__ float g_fA[(size_t)NMAX * 64];
__device__ float g_fB[(size_t)NMAX * 64];
__device__ float g_fC[(size_t)NMAX * 64];
__device__ float g_h1[(size_t)NMAX * 128];
__device__ float g_h2[(size_t)NMAX * 64];
__device__ float g_hlast_scratch[(size_t)NMAX * 128];
__device__ int   g_deg_out[NMAX];
__device__ int   g_deg_in[NMAX];
__device__ float g_snorm[NMAX];
__device__ float g_dnorm[NMAX];
__device__ int   g_rowptr[NMAX + 1];
__device__ int   g_cursor[NMAX];
__device__ int2  g_edges[EMAX];   // .x = src index, .y = bits of src_norm[src]

// ---------------- graph preprocessing ----------------
__global__ void k_zero_deg(int n) {
    int i = blockIdx.x * blockDim.x + threadIdx.x;
    if (i < n) { g_deg_out[i] = 0; g_deg_in[i] = 0; }
}

__global__ void k_degrees(const int* __restrict__ src, const int* __restrict__ dst, int e) {
    int i = blockIdx.x * blockDim.x + threadIdx.x;
    if (i < e) {
        atomicAdd(&g_deg_out[src[i]], 1);
        atomicAdd(&g_deg_in[dst[i]], 1);
    }
}

__global__ void k_norms(int n) {
    int i = blockIdx.x * blockDim.x + threadIdx.x;
    if (i < n) {
        int dout = g_deg_out[i];
        g_snorm[i] = (dout > 0) ? rsqrtf((float)dout) : 0.f;
        int din = g_deg_in[i];
        g_dnorm[i] = (din > 0) ? rsqrtf((float)din) : 0.f;
    }
}

// single-block inclusive scan over deg_in -> rowptr / cursor
__global__ void k_scan(int n) {
    __shared__ int sm[1024];
    __shared__ int carry_s;
    int t = threadIdx.x;
    if (t == 0) { carry_s = 0; g_rowptr[0] = 0; }
    __syncthreads();
    for (int base = 0; base < n; base += 1024) {
        int idx = base + t;
        int v = (idx < n) ? g_deg_in[idx] : 0;
        sm[t] = v;
        __syncthreads();
        #pragma unroll
        for (int off = 1; off < 1024; off <<= 1) {
            int add = (t >= off) ? sm[t - off] : 0;
            __syncthreads();
            sm[t] += add;
            __syncthreads();
        }
        int inc = sm[t];
        int carry = carry_s;
        if (idx < n) {
            g_rowptr[idx + 1] = carry + inc;
            g_cursor[idx]     = carry + inc - v;
        }
        __syncthreads();
        if (t == 1023) carry_s = carry + sm[1023];
        __syncthreads();
    }
}

__global__ void k_fill(const int* __restrict__ src, const int* __restrict__ dst, int e) {
    int i = blockIdx.x * blockDim.x + threadIdx.x;
    if (i < e) {
        int d = dst[i];
        int s = src[i];
        int p = atomicAdd(&g_cursor[d], 1);
        int2 v;
        v.x = s;
        v.y = __float_as_int(g_snorm[s]);
        g_edges[p] = v;
    }
}

// ---------------- APPNP propagation (pull model, 1 warp / node, float2 / lane) ----------------
__global__ void k_prop(const float* __restrict__ f, const float* __restrict__ f0,
                       float* __restrict__ fn, int n) {
    int node = blockIdx.x * (blockDim.x >> 5) + (threadIdx.x >> 5);
    if (node >= n) return;
    int lane = threadIdx.x & 31;
    int beg = g_rowptr[node];
    int end = g_rowptr[node + 1];
    float ax = 0.f, ay = 0.f;
    const float2* fp = (const float2*)f;
    for (int e = beg; e < end; e++) {
        int2 ev = __ldg(&g_edges[e]);
        float w = __int_as_float(ev.y);
        float2 v = __ldg(&fp[(size_t)ev.x * 32 + lane]);
        ax = fmaf(w, v.x, ax);
        ay = fmaf(w, v.y, ay);
    }
    float dn = 0.9f * g_dnorm[node];
    float2 b = __ldg((const float2*)f0 + (size_t)node * 32 + lane);
    float2 o;
    o.x = fmaf(dn, ax, 0.1f * b.x);
    o.y = fmaf(dn, ay, 0.1f * b.y);
    ((float2*)fn)[(size_t)node * 32 + lane] = o;
}

// ---------------- fused-tile fp32 GEMM: Y = act(X @ W + bias) ----------------
// X: [M,K] row-major, W: [K,Nout] row-major, Y: [M,Nout]. BN >= Nout; full Nout per block.
template<int BM, int BN, int BK, int TM, int TN, bool RELU>
__global__ void k_gemm(const float* __restrict__ X, const float* __restrict__ W,
                       const float* __restrict__ bias, float* __restrict__ Y,
                       int M, int Nout, int K) {
    constexpr int THREADS = (BM / TM) * (BN / TN);
    __shared__ float Xs[BK][BM + 4];
    __shared__ float Ws[BK][BN];
    int tid = threadIdx.x;
    int tx = tid % (BN / TN);
    int ty = tid / (BN / TN);
    int rowBase = blockIdx.x * BM;

    float acc[TM][TN];
    #pragma unroll
    for (int i = 0; i < TM; i++)
        #pragma unroll
        for (int j = 0; j < TN; j++) acc[i][j] = 0.f;

    for (int k0 = 0; k0 < K; k0 += BK) {
        // load X tile (BM x BK), transposed into smem
        #pragma unroll
        for (int i = tid; i < BM * (BK / 4); i += THREADS) {
            int m  = i / (BK / 4);
            int kq = i % (BK / 4);
            float4 v = make_float4(0.f, 0.f, 0.f, 0.f);
            int gm = rowBase + m;
            if (gm < M) v = *reinterpret_cast<const float4*>(&X[(size_t)gm * K + k0 + kq * 4]);
            Xs[kq * 4 + 0][m] = v.x;
            Xs[kq * 4 + 1][m] = v.y;
            Xs[kq * 4 + 2][m] = v.z;
            Xs[kq * 4 + 3][m] = v.w;
        }
        // load W tile (BK x BN), zero-pad cols >= Nout
        #pragma unroll
        for (int i = tid; i < BK * BN; i += THREADS) {
            int kk = i / BN, j = i % BN;
            float v = 0.f;
            if (j < Nout) v = W[(size_t)(k0 + kk) * Nout + j];
            Ws[kk][j] = v;
        }
        __syncthreads();
        #pragma unroll
        for (int kk = 0; kk < BK; kk++) {
            float a[TM], b[TN];
            #pragma unroll
            for (int i = 0; i < TM; i++) a[i] = Xs[kk][ty * TM + i];
            #pragma unroll
            for (int j = 0; j < TN; j++) b[j] = Ws[kk][tx * TN + j];
            #pragma unroll
            for (int i = 0; i < TM; i++)
                #pragma unroll
                for (int j = 0; j < TN; j++)
                    acc[i][j] = fmaf(a[i], b[j], acc[i][j]);
        }
        __syncthreads();
    }
    #pragma unroll
    for (int i = 0; i < TM; i++) {
        int gm = rowBase + ty * TM + i;
        if (gm >= M) continue;
        #pragma unroll
        for (int j = 0; j < TN; j++) {
            int gj = tx * TN + j;
            if (gj < Nout) {
                float v = acc[i][j] + bias[gj];
                if (RELU) v = fmaxf(v, 0.f);
                Y[(size_t)gm * Nout + gj] = v;
            }
        }
    }
}

// ---------------- launch ----------------
extern "C" void kernel_launch(void* const* d_in, const int* in_sizes, int n_in,
                              void* d_out, int out_size) {
    const float* input_feat = (const float*)d_in[0];
    const int*   src = (const int*)d_in[1];
    const int*   dst = (const int*)d_in[2];
    const float* W1  = (const float*)d_in[3];
    const float* b1  = (const float*)d_in[4];
    const float* W2  = (const float*)d_in[5];
    const float* b2  = (const float*)d_in[6];
    const float* Wh1 = (const float*)d_in[7];
    const float* bh1 = (const float*)d_in[8];
    const float* Wh2 = (const float*)d_in[9];
    const float* bh2 = (const float*)d_in[10];

    int n = in_sizes[0] / 64;
    int e = in_sizes[1];
    if (n > NMAX) n = NMAX;
    if (e > EMAX) e = EMAX;

    float* outp = (float*)d_out;

    float *fA, *fB, *fC, *h1p, *h2p, *hl_scratch;
    cudaGetSymbolAddress((void**)&fA, g_fA);
    cudaGetSymbolAddress((void**)&fB, g_fB);
    cudaGetSymbolAddress((void**)&fC, g_fC);
    cudaGetSymbolAddress((void**)&h1p, g_h1);
    cudaGetSymbolAddress((void**)&h2p, g_h2);
    cudaGetSymbolAddress((void**)&hl_scratch, g_hlast_scratch);

    // h_last goes straight into its d_out slot if present ([out, h_last] leaf order)
    float* hlast = (out_size >= n * 168) ? (outp + (size_t)n * 40) : hl_scratch;

    int nb = (n + 255) / 256;
    int eb = (e + 255) / 256;

    k_zero_deg<<<nb, 256>>>(n);
    k_degrees<<<eb, 256>>>(src, dst, e);
    k_norms<<<nb, 256>>>(n);
    k_scan<<<1, 1024>>>(n);
    k_fill<<<eb, 256>>>(src, dst, e);

    int pb = (n + 7) / 8;   // 8 nodes per 256-thread block

    // gnn1: feat0 = input_feat, ping-pong fA/fB (ends in fB)
    const float* f = input_feat;
    for (int s = 0; s < 10; s++) {
        float* o = (s % 2 == 0) ? fA : fB;
        k_prop<<<pb, 256>>>(f, input_feat, o, n);
        f = o;
    }
    // gnn2: feat0 = fB (persists), ping-pong fA/fC (ends in fC)
    const float* f02 = f;
    for (int s = 0; s < 10; s++) {
        float* o = (s % 2 == 0) ? fA : fC;
        k_prop<<<pb, 256>>>(f, f02, o, n);
        f = o;
    }

    int gridM = (n + 127) / 128;
    // L1: relu(fC @ W1 + b1) -> h1  [K=64, Nout=128]
    k_gemm<128, 128, 32, 8, 8, true><<<gridM, 256>>>(f, W1, b1, h1p, n, 128, 64);
    // L2: h1 @ W2 + b2 -> h_last    [K=128, Nout=128]
    k_gemm<128, 128, 32, 8, 8, false><<<gridM, 256>>>(h1p, W2, b2, hlast, n, 128, 128);
    // L3: relu(h_last @ Wh1 + bh1) -> h2  [K=128, Nout=64]
    k_gemm<128, 64, 32, 8, 8, true><<<gridM, 128>>>(hlast, Wh1, bh1, h2p, n, 64, 128);
    // L4: h2 @ Wh2 + bh2 -> out     [K=64, Nout=40 (padded to 64)]
    k_gemm<128, 64, 32, 8, 8, false><<<gridM, 128>>>(h2p, Wh2, bh2, outp, n, 40, 64);
}

// round 2
// speedup vs baseline: 1.2968x; 1.2968x over previous
#include <cuda_runtime.h>
#include <math.h>

#define NMAX 100000
#define EMAX 1000000

// ---------------- scratch (static device globals; no runtime allocation) ----------------
__device__ float g_fA[(size_t)NMAX * 64];
__device__ float g_fB[(size_t)NMAX * 64];
__device__ float g_fC[(size_t)NMAX * 64];
__device__ float g_h1[(size_t)NMAX * 128];
__device__ float g_h2[(size_t)NMAX * 64];
__device__ float g_hlast_scratch[(size_t)NMAX * 128];
__device__ int   g_deg_out[NMAX];
__device__ int   g_deg_in[NMAX];
__device__ float g_snorm[NMAX];
__device__ float g_dnorm[NMAX];
__device__ int   g_rowptr[NMAX + 1];
__device__ int   g_cursor[NMAX];
__device__ int   g_partials[128];
__device__ int2  g_edges[EMAX];   // .x = src index, .y = bits of src_norm[src]

// ---------------- graph preprocessing ----------------
__global__ void k_zero_deg(int n) {
    int i = blockIdx.x * blockDim.x + threadIdx.x;
    if (i < n) { g_deg_out[i] = 0; g_deg_in[i] = 0; }
}

__global__ void k_degrees(const int* __restrict__ src, const int* __restrict__ dst, int e) {
    int i = blockIdx.x * blockDim.x + threadIdx.x;
    if (i < e) {
        atomicAdd(&g_deg_out[src[i]], 1);
        atomicAdd(&g_deg_in[dst[i]], 1);
    }
}

__global__ void k_norms(int n) {
    int i = blockIdx.x * blockDim.x + threadIdx.x;
    if (i < n) {
        int dout = g_deg_out[i];
        g_snorm[i] = (dout > 0) ? rsqrtf((float)dout) : 0.f;
        int din = g_deg_in[i];
        g_dnorm[i] = (din > 0) ? rsqrtf((float)din) : 0.f;
    }
}

// ---------------- parallel scan: tile sums -> scan partials -> apply ----------------
__global__ void k_tile_sum(int n) {
    int idx = blockIdx.x * 1024 + threadIdx.x;
    int v = (idx < n) ? g_deg_in[idx] : 0;
    #pragma unroll
    for (int o = 16; o; o >>= 1) v += __shfl_down_sync(0xffffffffu, v, o);
    __shared__ int sm[32];
    if ((threadIdx.x & 31) == 0) sm[threadIdx.x >> 5] = v;
    __syncthreads();
    if (threadIdx.x < 32) {
        int s = sm[threadIdx.x];
        #pragma unroll
        for (int o = 16; o; o >>= 1) s += __shfl_down_sync(0xffffffffu, s, o);
        if (threadIdx.x == 0) g_partials[blockIdx.x] = s;
    }
}

__global__ void k_scan_partials(int ntiles) {
    int t = threadIdx.x;            // 128 threads
    int v = (t < ntiles) ? g_partials[t] : 0;
    int lane = t & 31, w = t >> 5;
    int x = v;
    #pragma unroll
    for (int o = 1; o < 32; o <<= 1) {
        int y = __shfl_up_sync(0xffffffffu, x, o);
        if (lane >= o) x += y;
    }
    __shared__ int ws[4];
    if (lane == 31) ws[w] = x;
    __syncthreads();
    if (t == 0) {
        int a = 0;
        #pragma unroll
        for (int i = 0; i < 4; i++) { int tmp = ws[i]; ws[i] = a; a += tmp; }
    }
    __syncthreads();
    int excl = x - v + ws[w];
    if (t < ntiles) g_partials[t] = excl;
}

__global__ void k_apply_scan(int n) {
    int tile = blockIdx.x;
    int t = threadIdx.x;
    int idx = tile * 1024 + t;
    int v = (idx < n) ? g_deg_in[idx] : 0;
    int lane = t & 31, w = t >> 5;
    int x = v;
    #pragma unroll
    for (int o = 1; o < 32; o <<= 1) {
        int y = __shfl_up_sync(0xffffffffu, x, o);
        if (lane >= o) x += y;
    }
    __shared__ int ws[32];
    if (lane == 31) ws[w] = x;
    __syncthreads();
    if (t < 32) {
        int y = ws[t];
        #pragma unroll
        for (int o = 1; o < 32; o <<= 1) {
            int z = __shfl_up_sync(0xffffffffu, y, o);
            if (lane >= o) y += z;
        }
        ws[t] = y;
    }
    __syncthreads();
    int winc = (w > 0) ? ws[w - 1] : 0;
    int inc = x + winc + g_partials[tile];
    if (idx < n) {
        g_rowptr[idx + 1] = inc;
        g_cursor[idx] = inc - v;
    }
    if (idx == 0) g_rowptr[0] = 0;
}

__global__ void k_fill(const int* __restrict__ src, const int* __restrict__ dst, int e) {
    int i = blockIdx.x * blockDim.x + threadIdx.x;
    if (i < e) {
        int d = dst[i];
        int s = src[i];
        int p = atomicAdd(&g_cursor[d], 1);
        int2 v;
        v.x = s;
        v.y = __float_as_int(g_snorm[s]);
        g_edges[p] = v;
    }
}

// ---------------- APPNP propagation: pull model, 1 warp/node, 4-edge pipelined ----------------
__global__ void __launch_bounds__(256) k_prop(
        const float* __restrict__ f, const float* __restrict__ f0,
        float* __restrict__ fn, int n) {
    int node = blockIdx.x * (blockDim.x >> 5) + (threadIdx.x >> 5);
    if (node >= n) return;
    int lane = threadIdx.x & 31;
    int beg = __ldg(&g_rowptr[node]);
    int end = __ldg(&g_rowptr[node + 1]);
    const float2* fp = (const float2*)f;
    float ax0 = 0.f, ay0 = 0.f, ax1 = 0.f, ay1 = 0.f;

    int e = beg;
    for (; e + 4 <= end; e += 4) {
        // 4 independent broadcast edge-record loads
        int2 e0 = __ldg(&g_edges[e + 0]);
        int2 e1 = __ldg(&g_edges[e + 1]);
        int2 e2 = __ldg(&g_edges[e + 2]);
        int2 e3 = __ldg(&g_edges[e + 3]);
        // 4 in-flight feature gathers
        float2 v0 = __ldg(&fp[(size_t)e0.x * 32 + lane]);
        float2 v1 = __ldg(&fp[(size_t)e1.x * 32 + lane]);
        float2 v2 = __ldg(&fp[(size_t)e2.x * 32 + lane]);
        float2 v3 = __ldg(&fp[(size_t)e3.x * 32 + lane]);
        float w0 = __int_as_float(e0.y);
        float w1 = __int_as_float(e1.y);
        float w2 = __int_as_float(e2.y);
        float w3 = __int_as_float(e3.y);
        ax0 = fmaf(w0, v0.x, ax0); ay0 = fmaf(w0, v0.y, ay0);
        ax1 = fmaf(w1, v1.x, ax1); ay1 = fmaf(w1, v1.y, ay1);
        ax0 = fmaf(w2, v2.x, ax0); ay0 = fmaf(w2, v2.y, ay0);
        ax1 = fmaf(w3, v3.x, ax1); ay1 = fmaf(w3, v3.y, ay1);
    }
    for (; e < end; e++) {
        int2 ev = __ldg(&g_edges[e]);
        float w = __int_as_float(ev.y);
        float2 v = __ldg(&fp[(size_t)ev.x * 32 + lane]);
        ax0 = fmaf(w, v.x, ax0);
        ay0 = fmaf(w, v.y, ay0);
    }
    float ax = ax0 + ax1, ay = ay0 + ay1;
    float dn = 0.9f * __ldg(&g_dnorm[node]);
    float2 b = __ldg((const float2*)f0 + (size_t)node * 32 + lane);
    float2 o;
    o.x = fmaf(dn, ax, 0.1f * b.x);
    o.y = fmaf(dn, ay, 0.1f * b.y);
    ((float2*)fn)[(size_t)node * 32 + lane] = o;
}

// ---------------- fused-tile fp32 GEMM: Y = act(X @ W + bias) ----------------
template<int BM, int BN, int BK, int TM, int TN, bool RELU>
__global__ void k_gemm(const float* __restrict__ X, const float* __restrict__ W,
                       const float* __restrict__ bias, float* __restrict__ Y,
                       int M, int Nout, int K) {
    constexpr int THREADS = (BM / TM) * (BN / TN);
    __shared__ float Xs[BK][BM + 4];
    __shared__ float Ws[BK][BN];
    int tid = threadIdx.x;
    int tx = tid % (BN / TN);
    int ty = tid / (BN / TN);
    int rowBase = blockIdx.x * BM;

    float acc[TM][TN];
    #pragma unroll
    for (int i = 0; i < TM; i++)
        #pragma unroll
        for (int j = 0; j < TN; j++) acc[i][j] = 0.f;

    for (int k0 = 0; k0 < K; k0 += BK) {
        #pragma unroll
        for (int i = tid; i < BM * (BK / 4); i += THREADS) {
            int m  = i / (BK / 4);
            int kq = i % (BK / 4);
            float4 v = make_float4(0.f, 0.f, 0.f, 0.f);
            int gm = rowBase + m;
            if (gm < M) v = *reinterpret_cast<const float4*>(&X[(size_t)gm * K + k0 + kq * 4]);
            Xs[kq * 4 + 0][m] = v.x;
            Xs[kq * 4 + 1][m] = v.y;
            Xs[kq * 4 + 2][m] = v.z;
            Xs[kq * 4 + 3][m] = v.w;
        }
        #pragma unroll
        for (int i = tid; i < BK * BN; i += THREADS) {
            int kk = i / BN, j = i % BN;
            float v = 0.f;
            if (j < Nout) v = W[(size_t)(k0 + kk) * Nout + j];
            Ws[kk][j] = v;
        }
        __syncthreads();
        #pragma unroll
        for (int kk = 0; kk < BK; kk++) {
            float a[TM], b[TN];
            #pragma unroll
            for (int i = 0; i < TM; i++) a[i] = Xs[kk][ty * TM + i];
            #pragma unroll
            for (int j = 0; j < TN; j++) b[j] = Ws[kk][tx * TN + j];
            #pragma unroll
            for (int i = 0; i < TM; i++)
                #pragma unroll
                for (int j = 0; j < TN; j++)
                    acc[i][j] = fmaf(a[i], b[j], acc[i][j]);
        }
        __syncthreads();
    }
    #pragma unroll
    for (int i = 0; i < TM; i++) {
        int gm = rowBase + ty * TM + i;
        if (gm >= M) continue;
        #pragma unroll
        for (int j = 0; j < TN; j++) {
            int gj = tx * TN + j;
            if (gj < Nout) {
                float v = acc[i][j] + bias[gj];
                if (RELU) v = fmaxf(v, 0.f);
                Y[(size_t)gm * Nout + gj] = v;
            }
        }
    }
}

// ---------------- launch ----------------
extern "C" void kernel_launch(void* const* d_in, const int* in_sizes, int n_in,
                              void* d_out, int out_size) {
    const float* input_feat = (const float*)d_in[0];
    const int*   src = (const int*)d_in[1];
    const int*   dst = (const int*)d_in[2];
    const float* W1  = (const float*)d_in[3];
    const float* b1  = (const float*)d_in[4];
    const float* W2  = (const float*)d_in[5];
    const float* b2  = (const float*)d_in[6];
    const float* Wh1 = (const float*)d_in[7];
    const float* bh1 = (const float*)d_in[8];
    const float* Wh2 = (const float*)d_in[9];
    const float* bh2 = (const float*)d_in[10];

    int n = in_sizes[0] / 64;
    int e = in_sizes[1];
    if (n > NMAX) n = NMAX;
    if (e > EMAX) e = EMAX;

    float* outp = (float*)d_out;

    float *fA, *fB, *fC, *h1p, *h2p, *hl_scratch;
    cudaGetSymbolAddress((void**)&fA, g_fA);
    cudaGetSymbolAddress((void**)&fB, g_fB);
    cudaGetSymbolAddress((void**)&fC, g_fC);
    cudaGetSymbolAddress((void**)&h1p, g_h1);
    cudaGetSymbolAddress((void**)&h2p, g_h2);
    cudaGetSymbolAddress((void**)&hl_scratch, g_hlast_scratch);

    float* hlast = (out_size >= n * 168) ? (outp + (size_t)n * 40) : hl_scratch;

    int nb = (n + 255) / 256;
    int eb = (e + 255) / 256;
    int ntiles = (n + 1023) / 1024;

    k_zero_deg<<<nb, 256>>>(n);
    k_degrees<<<eb, 256>>>(src, dst, e);
    k_norms<<<nb, 256>>>(n);
    k_tile_sum<<<ntiles, 1024>>>(n);
    k_scan_partials<<<1, 128>>>(ntiles);
    k_apply_scan<<<ntiles, 1024>>>(n);
    k_fill<<<eb, 256>>>(src, dst, e);

    int pb = (n + 7) / 8;   // 8 nodes per 256-thread block

    // gnn1: feat0 = input_feat, ping-pong fA/fB (ends in fB)
    const float* f = input_feat;
    for (int s = 0; s < 10; s++) {
        float* o = (s % 2 == 0) ? fA : fB;
        k_prop<<<pb, 256>>>(f, input_feat, o, n);
        f = o;
    }
    // gnn2: feat0 = fB (persists), ping-pong fA/fC (ends in fC)
    const float* f02 = f;
    for (int s = 0; s < 10; s++) {
        float* o = (s % 2 == 0) ? fA : fC;
        k_prop<<<pb, 256>>>(f, f02, o, n);
        f = o;
    }

    int gridM = (n + 127) / 128;
    k_gemm<128, 128, 32, 8, 8, true ><<<gridM, 256>>>(f,     W1,  b1,  h1p,   n, 128,  64);
    k_gemm<128, 128, 32, 8, 8, false><<<gridM, 256>>>(h1p,   W2,  b2,  hlast, n, 128, 128);
    k_gemm<128,  64, 32, 8, 8, true ><<<gridM, 128>>>(hlast, Wh1, bh1, h2p,   n,  64, 128);
    k_gemm<128,  64, 32, 8, 8, false><<<gridM, 128>>>(h2p,   Wh2, bh2, outp,  n,  40,  64);
}

// round 4
// speedup vs baseline: 1.5279x; 1.1782x over previous
#include <cuda_runtime.h>
#include <math.h>

#define NMAX 100000
#define EMAX 1000000

// ---------------- scratch (static device globals; float4-typed => 16B aligned) ----------------
__device__ float4 g_fA[(size_t)NMAX * 16];
__device__ float4 g_fB[(size_t)NMAX * 16];
__device__ float4 g_fC[(size_t)NMAX * 16];
__device__ float4 g_h1[(size_t)NMAX * 32];
__device__ float4 g_h2[(size_t)NMAX * 16];
__device__ float4 g_hlast_scratch[(size_t)NMAX * 32];
__device__ int    g_deg_out[NMAX];
__device__ int    g_deg_in[NMAX];
__device__ float  g_snorm[NMAX];
__device__ float  g_dnorm[NMAX];
__device__ int    g_rowptr[NMAX + 1];
__device__ int    g_cursor[NMAX];
__device__ int    g_partials[128];
__device__ int2   g_edges[EMAX];   // .x = src index, .y = bits of src_norm[src]

// ---------------- graph preprocessing ----------------
__global__ void k_zero_deg(int n) {
    int i = blockIdx.x * blockDim.x + threadIdx.x;
    if (i < n) { g_deg_out[i] = 0; g_deg_in[i] = 0; }
}

__global__ void k_degrees(const int* __restrict__ src, const int* __restrict__ dst, int e) {
    int i = blockIdx.x * blockDim.x + threadIdx.x;
    if (i < e) {
        atomicAdd(&g_deg_out[src[i]], 1);
        atomicAdd(&g_deg_in[dst[i]], 1);
    }
}

// norms + per-tile deg_in sums, fused (uniform barriers only)
__global__ void k_norms_tilesum(int n) {
    int idx = blockIdx.x * 1024 + threadIdx.x;
    int din = 0;
    if (idx < n) {
        int dout = g_deg_out[idx];
        g_snorm[idx] = (dout > 0) ? rsqrtf((float)dout) : 0.f;
        din = g_deg_in[idx];
        g_dnorm[idx] = (din > 0) ? rsqrtf((float)din) : 0.f;
    }
    int v = din;
    #pragma unroll
    for (int o = 16; o; o >>= 1) v += __shfl_down_sync(0xffffffffu, v, o);
    __shared__ int sm[32];
    if ((threadIdx.x & 31) == 0) sm[threadIdx.x >> 5] = v;
    __syncthreads();
    if (threadIdx.x < 32) {
        int s = sm[threadIdx.x];
        #pragma unroll
        for (int o = 16; o; o >>= 1) s += __shfl_down_sync(0xffffffffu, s, o);
        if (threadIdx.x == 0) g_partials[blockIdx.x] = s;
    }
}

// single block, 128 threads: exclusive scan of tile partials (known-good R2 version)
__global__ void k_scan_partials(int ntiles) {
    int t = threadIdx.x;
    int v = (t < ntiles) ? g_partials[t] : 0;
    int lane = t & 31, w = t >> 5;
    int x = v;
    #pragma unroll
    for (int o = 1; o < 32; o <<= 1) {
        int y = __shfl_up_sync(0xffffffffu, x, o);
        if (lane >= o) x += y;
    }
    __shared__ int ws[4];
    if (lane == 31) ws[w] = x;
    __syncthreads();
    if (t == 0) {
        int a = 0;
        #pragma unroll
        for (int i = 0; i < 4; i++) { int tmp = ws[i]; ws[i] = a; a += tmp; }
    }
    __syncthreads();
    int excl = x - v + ws[w];
    if (t < ntiles) g_partials[t] = excl;
}

// apply scan (known-good R2 version; uniform barriers)
__global__ void k_apply_scan(int n) {
    int tile = blockIdx.x;
    int t = threadIdx.x;
    int idx = tile * 1024 + t;
    int v = (idx < n) ? g_deg_in[idx] : 0;
    int lane = t & 31, w = t >> 5;
    int x = v;
    #pragma unroll
    for (int o = 1; o < 32; o <<= 1) {
        int y = __shfl_up_sync(0xffffffffu, x, o);
        if (lane >= o) x += y;
    }
    __shared__ int ws[32];
    if (lane == 31) ws[w] = x;
    __syncthreads();
    if (t < 32) {
        int y = ws[t];
        #pragma unroll
        for (int o = 1; o < 32; o <<= 1) {
            int z = __shfl_up_sync(0xffffffffu, y, o);
            if (lane >= o) y += z;
        }
        ws[t] = y;
    }
    __syncthreads();
    int winc = (w > 0) ? ws[w - 1] : 0;
    int inc = x + winc + g_partials[tile];
    if (idx < n) {
        g_rowptr[idx + 1] = inc;
        g_cursor[idx] = inc - v;
    }
    if (idx == 0) g_rowptr[0] = 0;
}

__global__ void k_fill(const int* __restrict__ src, const int* __restrict__ dst, int e) {
    int i = blockIdx.x * blockDim.x + threadIdx.x;
    if (i < e) {
        int d = dst[i];
        int s = src[i];
        int p = atomicAdd(&g_cursor[d], 1);
        int2 v;
        v.x = s;
        v.y = __float_as_int(g_snorm[s]);
        g_edges[p] = v;
    }
}

// ---------------- APPNP propagation: half-warp/node, float4/lane, 4-edge pipelined ----------------
__global__ void __launch_bounds__(256) k_prop(
        const float4* __restrict__ fp, const float4* __restrict__ f0,
        float4* __restrict__ fn, int n) {
    int node = blockIdx.x * 16 + (threadIdx.x >> 4);
    if (node >= n) return;
    int lane = threadIdx.x & 15;
    int beg = __ldg(&g_rowptr[node]);
    int end = __ldg(&g_rowptr[node + 1]);

    float4 a0 = make_float4(0.f, 0.f, 0.f, 0.f);
    float4 a1 = make_float4(0.f, 0.f, 0.f, 0.f);

    int e = beg;
    for (; e + 4 <= end; e += 4) {
        int2 e0 = __ldg(&g_edges[e + 0]);
        int2 e1 = __ldg(&g_edges[e + 1]);
        int2 e2 = __ldg(&g_edges[e + 2]);
        int2 e3 = __ldg(&g_edges[e + 3]);
        float4 v0 = __ldg(&fp[(size_t)e0.x * 16 + lane]);
        float4 v1 = __ldg(&fp[(size_t)e1.x * 16 + lane]);
        float4 v2 = __ldg(&fp[(size_t)e2.x * 16 + lane]);
        float4 v3 = __ldg(&fp[(size_t)e3.x * 16 + lane]);
        float w0 = __int_as_float(e0.y);
        float w1 = __int_as_float(e1.y);
        float w2 = __int_as_float(e2.y);
        float w3 = __int_as_float(e3.y);
        a0.x = fmaf(w0, v0.x, a0.x); a0.y = fmaf(w0, v0.y, a0.y);
        a0.z = fmaf(w0, v0.z, a0.z); a0.w = fmaf(w0, v0.w, a0.w);
        a1.x = fmaf(w1, v1.x, a1.x); a1.y = fmaf(w1, v1.y, a1.y);
        a1.z = fmaf(w1, v1.z, a1.z); a1.w = fmaf(w1, v1.w, a1.w);
        a0.x = fmaf(w2, v2.x, a0.x); a0.y = fmaf(w2, v2.y, a0.y);
        a0.z = fmaf(w2, v2.z, a0.z); a0.w = fmaf(w2, v2.w, a0.w);
        a1.x = fmaf(w3, v3.x, a1.x); a1.y = fmaf(w3, v3.y, a1.y);
        a1.z = fmaf(w3, v3.z, a1.z); a1.w = fmaf(w3, v3.w, a1.w);
    }
    for (; e < end; e++) {
        int2 ev = __ldg(&g_edges[e]);
        float w = __int_as_float(ev.y);
        float4 v = __ldg(&fp[(size_t)ev.x * 16 + lane]);
        a0.x = fmaf(w, v.x, a0.x); a0.y = fmaf(w, v.y, a0.y);
        a0.z = fmaf(w, v.z, a0.z); a0.w = fmaf(w, v.w, a0.w);
    }
    float ax = a0.x + a1.x, ay = a0.y + a1.y;
    float az = a0.z + a1.z, aw = a0.w + a1.w;

    float dn = 0.9f * __ldg(&g_dnorm[node]);
    float4 b = __ldg(&f0[(size_t)node * 16 + lane]);
    float4 o;
    o.x = fmaf(dn, ax, 0.1f * b.x);
    o.y = fmaf(dn, ay, 0.1f * b.y);
    o.z = fmaf(dn, az, 0.1f * b.z);
    o.w = fmaf(dn, aw, 0.1f * b.w);
    fn[(size_t)node * 16 + lane] = o;
}

// ---------------- fused-tile fp32 GEMM: Y = act(X @ W + bias) ----------------
template<int BM, int BN, int BK, int TM, int TN, bool RELU>
__global__ void k_gemm(const float* __restrict__ X, const float* __restrict__ W,
                       const float* __restrict__ bias, float* __restrict__ Y,
                       int M, int Nout, int K) {
    constexpr int THREADS = (BM / TM) * (BN / TN);
    __shared__ float Xs[BK][BM + 4];
    __shared__ float Ws[BK][BN];
    int tid = threadIdx.x;
    int tx = tid % (BN / TN);
    int ty = tid / (BN / TN);
    int rowBase = blockIdx.x * BM;

    float acc[TM][TN];
    #pragma unroll
    for (int i = 0; i < TM; i++)
        #pragma unroll
        for (int j = 0; j < TN; j++) acc[i][j] = 0.f;

    for (int k0 = 0; k0 < K; k0 += BK) {
        #pragma unroll
        for (int i = tid; i < BM * (BK / 4); i += THREADS) {
            int m  = i / (BK / 4);
            int kq = i % (BK / 4);
            float4 v = make_float4(0.f, 0.f, 0.f, 0.f);
            int gm = rowBase + m;
            if (gm < M) v = *reinterpret_cast<const float4*>(&X[(size_t)gm * K + k0 + kq * 4]);
            Xs[kq * 4 + 0][m] = v.x;
            Xs[kq * 4 + 1][m] = v.y;
            Xs[kq * 4 + 2][m] = v.z;
            Xs[kq * 4 + 3][m] = v.w;
        }
        #pragma unroll
        for (int i = tid; i < BK * BN; i += THREADS) {
            int kk = i / BN, j = i % BN;
            float v = 0.f;
            if (j < Nout) v = W[(size_t)(k0 + kk) * Nout + j];
            Ws[kk][j] = v;
        }
        __syncthreads();
        #pragma unroll
        for (int kk = 0; kk < BK; kk++) {
            float a[TM], b[TN];
            #pragma unroll
            for (int i = 0; i < TM; i++) a[i] = Xs[kk][ty * TM + i];
            #pragma unroll
            for (int j = 0; j < TN; j++) b[j] = Ws[kk][tx * TN + j];
            #pragma unroll
            for (int i = 0; i < TM; i++)
                #pragma unroll
                for (int j = 0; j < TN; j++)
                    acc[i][j] = fmaf(a[i], b[j], acc[i][j]);
        }
        __syncthreads();
    }
    #pragma unroll
    for (int i = 0; i < TM; i++) {
        int gm = rowBase + ty * TM + i;
        if (gm >= M) continue;
        #pragma unroll
        for (int j = 0; j < TN; j++) {
            int gj = tx * TN + j;
            if (gj < Nout) {
                float v = acc[i][j] + bias[gj];
                if (RELU) v = fmaxf(v, 0.f);
                Y[(size_t)gm * Nout + gj] = v;
            }
        }
    }
}

// ---------------- launch ----------------
extern "C" void kernel_launch(void* const* d_in, const int* in_sizes, int n_in,
                              void* d_out, int out_size) {
    const float* input_feat = (const float*)d_in[0];
    const int*   src = (const int*)d_in[1];
    const int*   dst = (const int*)d_in[2];
    const float* W1  = (const float*)d_in[3];
    const float* b1  = (const float*)d_in[4];
    const float* W2  = (const float*)d_in[5];
    const float* b2  = (const float*)d_in[6];
    const float* Wh1 = (const float*)d_in[7];
    const float* bh1 = (const float*)d_in[8];
    const float* Wh2 = (const float*)d_in[9];
    const float* bh2 = (const float*)d_in[10];

    int n = in_sizes[0] / 64;
    int e = in_sizes[1];
    if (n > NMAX) n = NMAX;
    if (e > EMAX) e = EMAX;

    float* outp = (float*)d_out;

    float4 *fA, *fB, *fC, *h1p, *h2p, *hl_scratch;
    cudaGetSymbolAddress((void**)&fA, g_fA);
    cudaGetSymbolAddress((void**)&fB, g_fB);
    cudaGetSymbolAddress((void**)&fC, g_fC);
    cudaGetSymbolAddress((void**)&h1p, g_h1);
    cudaGetSymbolAddress((void**)&h2p, g_h2);
    cudaGetSymbolAddress((void**)&hl_scratch, g_hlast_scratch);

    float* hlast = (out_size >= n * 168) ? (outp + (size_t)n * 40) : (float*)hl_scratch;

    int nb = (n + 255) / 256;
    int eb = (e + 255) / 256;
    int ntiles = (n + 1023) / 1024;

    k_zero_deg<<<nb, 256>>>(n);
    k_degrees<<<eb, 256>>>(src, dst, e);
    k_norms_tilesum<<<ntiles, 1024>>>(n);
    k_scan_partials<<<1, 128>>>(ntiles);
    k_apply_scan<<<ntiles, 1024>>>(n);
    k_fill<<<eb, 256>>>(src, dst, e);

    int pb = (n + 15) / 16;   // 16 nodes per 256-thread block (half-warp per node)

    // gnn1: feat0 = input_feat, ping-pong fA/fB (ends in fB)
    const float4* f = (const float4*)input_feat;
    const float4* f01 = (const float4*)input_feat;
    for (int s = 0; s < 10; s++) {
        float4* o = (s % 2 == 0) ? fA : fB;
        k_prop<<<pb, 256>>>(f, f01, o, n);
        f = o;
    }
    // gnn2: feat0 = fB (persists), ping-pong fA/fC (ends in fC)
    const float4* f02 = f;
    for (int s = 0; s < 10; s++) {
        float4* o = (s % 2 == 0) ? fA : fC;
        k_prop<<<pb, 256>>>(f, f02, o, n);
        f = o;
    }

    int gridM = (n + 127) / 128;
    k_gemm<128, 128, 32, 8, 8, true ><<<gridM, 256>>>((const float*)f, W1,  b1,  (float*)h1p, n, 128,  64);
    k_gemm<128, 128, 32, 8, 8, false><<<gridM, 256>>>((const float*)h1p, W2,  b2,  hlast,     n, 128, 128);
    k_gemm<128,  64, 32, 8, 8, true ><<<gridM, 128>>>(hlast, Wh1, bh1, (float*)h2p, n,  64, 128);
    k_gemm<128,  64, 32, 8, 8, false><<<gridM, 128>>>((const float*)h2p, Wh2, bh2, outp, n, 40, 64);
}

// round 5
// speedup vs baseline: 1.6514x; 1.0808x over previous
#include <cuda_runtime.h>
#include <math.h>
#include <stdint.h>

#define NMAX 100000
#define EMAX 1000000

// ---------------- scratch (static device globals; float4-typed => 16B aligned) ----------------
__device__ float4 g_fA[(size_t)NMAX * 16];
__device__ float4 g_fB[(size_t)NMAX * 16];
__device__ float4 g_fC[(size_t)NMAX * 16];
__device__ float4 g_h1[(size_t)NMAX * 32];
__device__ float4 g_h2[(size_t)NMAX * 16];
__device__ float4 g_hlast_scratch[(size_t)NMAX * 32];
__device__ int    g_deg_out[NMAX];
__device__ int    g_deg_in[NMAX];
__device__ float  g_snorm[NMAX];
__device__ float  g_dnorm[NMAX];
__device__ int    g_rowptr[NMAX + 1];
__device__ int    g_cursor[NMAX];
__device__ int    g_partials[128];
__device__ int2   g_edges[EMAX];   // .x = src index, .y = bits of src_norm[src]

// ---------------- graph preprocessing ----------------
__global__ void k_zero_deg(int n) {
    int i = blockIdx.x * blockDim.x + threadIdx.x;
    if (i < n) { g_deg_out[i] = 0; g_deg_in[i] = 0; }
}

__global__ void k_degrees(const int* __restrict__ src, const int* __restrict__ dst, int e) {
    int i = blockIdx.x * blockDim.x + threadIdx.x;
    if (i < e) {
        atomicAdd(&g_deg_out[src[i]], 1);
        atomicAdd(&g_deg_in[dst[i]], 1);
    }
}

__global__ void k_norms_tilesum(int n) {
    int idx = blockIdx.x * 1024 + threadIdx.x;
    int din = 0;
    if (idx < n) {
        int dout = g_deg_out[idx];
        g_snorm[idx] = (dout > 0) ? rsqrtf((float)dout) : 0.f;
        din = g_deg_in[idx];
        g_dnorm[idx] = (din > 0) ? rsqrtf((float)din) : 0.f;
    }
    int v = din;
    #pragma unroll
    for (int o = 16; o; o >>= 1) v += __shfl_down_sync(0xffffffffu, v, o);
    __shared__ int sm[32];
    if ((threadIdx.x & 31) == 0) sm[threadIdx.x >> 5] = v;
    __syncthreads();
    if (threadIdx.x < 32) {
        int s = sm[threadIdx.x];
        #pragma unroll
        for (int o = 16; o; o >>= 1) s += __shfl_down_sync(0xffffffffu, s, o);
        if (threadIdx.x == 0) g_partials[blockIdx.x] = s;
    }
}

__global__ void k_scan_partials(int ntiles) {
    int t = threadIdx.x;
    int v = (t < ntiles) ? g_partials[t] : 0;
    int lane = t & 31, w = t >> 5;
    int x = v;
    #pragma unroll
    for (int o = 1; o < 32; o <<= 1) {
        int y = __shfl_up_sync(0xffffffffu, x, o);
        if (lane >= o) x += y;
    }
    __shared__ int ws[4];
    if (lane == 31) ws[w] = x;
    __syncthreads();
    if (t == 0) {
        int a = 0;
        #pragma unroll
        for (int i = 0; i < 4; i++) { int tmp = ws[i]; ws[i] = a; a += tmp; }
    }
    __syncthreads();
    int excl = x - v + ws[w];
    if (t < ntiles) g_partials[t] = excl;
}

__global__ void k_apply_scan(int n) {
    int tile = blockIdx.x;
    int t = threadIdx.x;
    int idx = tile * 1024 + t;
    int v = (idx < n) ? g_deg_in[idx] : 0;
    int lane = t & 31, w = t >> 5;
    int x = v;
    #pragma unroll
    for (int o = 1; o < 32; o <<= 1) {
        int y = __shfl_up_sync(0xffffffffu, x, o);
        if (lane >= o) x += y;
    }
    __shared__ int ws[32];
    if (lane == 31) ws[w] = x;
    __syncthreads();
    if (t < 32) {
        int y = ws[t];
        #pragma unroll
        for (int o = 1; o < 32; o <<= 1) {
            int z = __shfl_up_sync(0xffffffffu, y, o);
            if (lane >= o) y += z;
        }
        ws[t] = y;
    }
    __syncthreads();
    int winc = (w > 0) ? ws[w - 1] : 0;
    int inc = x + winc + g_partials[tile];
    if (idx < n) {
        g_rowptr[idx + 1] = inc;
        g_cursor[idx] = inc - v;
    }
    if (idx == 0) g_rowptr[0] = 0;
}

__global__ void k_fill(const int* __restrict__ src, const int* __restrict__ dst, int e) {
    int i = blockIdx.x * blockDim.x + threadIdx.x;
    if (i < e) {
        int d = dst[i];
        int s = src[i];
        int p = atomicAdd(&g_cursor[d], 1);
        int2 v;
        v.x = s;
        v.y = __float_as_int(g_snorm[s]);
        g_edges[p] = v;
    }
}

// ---------------- APPNP propagation: half-warp/node, float4/lane, 8-edge pipelined ----------------
#define PROP_FMA4(A, W, V) \
    A.x = fmaf(W, V.x, A.x); A.y = fmaf(W, V.y, A.y); \
    A.z = fmaf(W, V.z, A.z); A.w = fmaf(W, V.w, A.w);

__global__ void __launch_bounds__(256) k_prop(
        const float4* __restrict__ fp, const float4* __restrict__ f0,
        float4* __restrict__ fn, int n) {
    int node = blockIdx.x * 16 + (threadIdx.x >> 4);
    if (node >= n) return;
    int lane = threadIdx.x & 15;
    int beg = __ldg(&g_rowptr[node]);
    int end = __ldg(&g_rowptr[node + 1]);

    float4 a0 = make_float4(0.f, 0.f, 0.f, 0.f);
    float4 a1 = make_float4(0.f, 0.f, 0.f, 0.f);

    int e = beg;
    for (; e + 8 <= end; e += 8) {
        int2 e0 = __ldg(&g_edges[e + 0]);
        int2 e1 = __ldg(&g_edges[e + 1]);
        int2 e2 = __ldg(&g_edges[e + 2]);
        int2 e3 = __ldg(&g_edges[e + 3]);
        int2 e4 = __ldg(&g_edges[e + 4]);
        int2 e5 = __ldg(&g_edges[e + 5]);
        int2 e6 = __ldg(&g_edges[e + 6]);
        int2 e7 = __ldg(&g_edges[e + 7]);
        float4 v0 = __ldg(&fp[(size_t)e0.x * 16 + lane]);
        float4 v1 = __ldg(&fp[(size_t)e1.x * 16 + lane]);
        float4 v2 = __ldg(&fp[(size_t)e2.x * 16 + lane]);
        float4 v3 = __ldg(&fp[(size_t)e3.x * 16 + lane]);
        float4 v4 = __ldg(&fp[(size_t)e4.x * 16 + lane]);
        float4 v5 = __ldg(&fp[(size_t)e5.x * 16 + lane]);
        float4 v6 = __ldg(&fp[(size_t)e6.x * 16 + lane]);
        float4 v7 = __ldg(&fp[(size_t)e7.x * 16 + lane]);
        float w0 = __int_as_float(e0.y), w1 = __int_as_float(e1.y);
        float w2 = __int_as_float(e2.y), w3 = __int_as_float(e3.y);
        float w4 = __int_as_float(e4.y), w5 = __int_as_float(e5.y);
        float w6 = __int_as_float(e6.y), w7 = __int_as_float(e7.y);
        PROP_FMA4(a0, w0, v0); PROP_FMA4(a1, w1, v1);
        PROP_FMA4(a0, w2, v2); PROP_FMA4(a1, w3, v3);
        PROP_FMA4(a0, w4, v4); PROP_FMA4(a1, w5, v5);
        PROP_FMA4(a0, w6, v6); PROP_FMA4(a1, w7, v7);
    }
    for (; e + 4 <= end; e += 4) {
        int2 e0 = __ldg(&g_edges[e + 0]);
        int2 e1 = __ldg(&g_edges[e + 1]);
        int2 e2 = __ldg(&g_edges[e + 2]);
        int2 e3 = __ldg(&g_edges[e + 3]);
        float4 v0 = __ldg(&fp[(size_t)e0.x * 16 + lane]);
        float4 v1 = __ldg(&fp[(size_t)e1.x * 16 + lane]);
        float4 v2 = __ldg(&fp[(size_t)e2.x * 16 + lane]);
        float4 v3 = __ldg(&fp[(size_t)e3.x * 16 + lane]);
        float w0 = __int_as_float(e0.y), w1 = __int_as_float(e1.y);
        float w2 = __int_as_float(e2.y), w3 = __int_as_float(e3.y);
        PROP_FMA4(a0, w0, v0); PROP_FMA4(a1, w1, v1);
        PROP_FMA4(a0, w2, v2); PROP_FMA4(a1, w3, v3);
    }
    for (; e < end; e++) {
        int2 ev = __ldg(&g_edges[e]);
        float w = __int_as_float(ev.y);
        float4 v = __ldg(&fp[(size_t)ev.x * 16 + lane]);
        PROP_FMA4(a0, w, v);
    }
    float ax = a0.x + a1.x, ay = a0.y + a1.y;
    float az = a0.z + a1.z, aw = a0.w + a1.w;

    float dn = 0.9f * __ldg(&g_dnorm[node]);
    float4 b = __ldg(&f0[(size_t)node * 16 + lane]);
    float4 o;
    o.x = fmaf(dn, ax, 0.1f * b.x);
    o.y = fmaf(dn, ay, 0.1f * b.y);
    o.z = fmaf(dn, az, 0.1f * b.z);
    o.w = fmaf(dn, aw, 0.1f * b.w);
    fn[(size_t)node * 16 + lane] = o;
}

// ---------------- tf32 tensor-core GEMM: Y = act(X @ W + bias) ----------------
// X [M,K] row-major fp32, W [K,Nout] row-major fp32, Y [M,Nout].
// Block tile: 128 x BN, BK=32, 256 threads = 8 warps arranged 4(M) x 2(N).
__device__ __forceinline__ uint32_t f2tf32(float v) {
    uint32_t u;
    asm("cvt.rna.tf32.f32 %0, %1;" : "=r"(u) : "f"(v));
    return u;
}

template<int BN, bool RELU>
__global__ void __launch_bounds__(256) k_gemm_tf32(
        const float* __restrict__ X, const float* __restrict__ W,
        const float* __restrict__ bias, float* __restrict__ Y,
        int M, int Nout, int K) {
    constexpr int BM = 128;
    constexpr int BK = 32;
    constexpr int WSPAN_N = BN / 2;       // warp n-span
    constexpr int NF = WSPAN_N / 8;       // n-frags per warp
    constexpr int MF = 2;                 // m-frags per warp (2 x 16 = 32 rows)

    __shared__ uint32_t Xs[BK][BM + 4];   // tf32 bits, [k][m]
    __shared__ uint32_t Ws[BK][BN + 4];   // tf32 bits, [k][n]

    int tid = threadIdx.x;
    int wid = tid >> 5;
    int lane = tid & 31;
    int g = lane >> 2;          // groupID 0..7
    int tg = lane & 3;          // thread-in-group 0..3
    int wm = wid & 3;           // warp m index 0..3
    int wn = wid >> 2;          // warp n index 0..1
    int rowBase = blockIdx.x * BM;

    float acc[MF][NF][4];
    #pragma unroll
    for (int i = 0; i < MF; i++)
        #pragma unroll
        for (int j = 0; j < NF; j++)
            #pragma unroll
            for (int r = 0; r < 4; r++) acc[i][j][r] = 0.f;

    for (int k0 = 0; k0 < K; k0 += BK) {
        // X tile: BM x BK, transposed into Xs[k][m]; float4 loads along k
        #pragma unroll
        for (int i = tid; i < BM * (BK / 4); i += 256) {
            int m  = i / (BK / 4);
            int kq = i % (BK / 4);
            float4 v = make_float4(0.f, 0.f, 0.f, 0.f);
            int gm = rowBase + m;
            if (gm < M) v = *reinterpret_cast<const float4*>(&X[(size_t)gm * K + k0 + kq * 4]);
            Xs[kq * 4 + 0][m] = f2tf32(v.x);
            Xs[kq * 4 + 1][m] = f2tf32(v.y);
            Xs[kq * 4 + 2][m] = f2tf32(v.z);
            Xs[kq * 4 + 3][m] = f2tf32(v.w);
        }
        // W tile: BK x BN
        #pragma unroll
        for (int i = tid; i < BK * BN; i += 256) {
            int kk = i / BN, j = i % BN;
            float v = 0.f;
            if (j < Nout) v = W[(size_t)(k0 + kk) * Nout + j];
            Ws[kk][j] = f2tf32(v);
        }
        __syncthreads();

        #pragma unroll
        for (int kk = 0; kk < BK; kk += 8) {
            uint32_t afr[MF][4];
            #pragma unroll
            for (int mf = 0; mf < MF; mf++) {
                int mr = wm * 32 + mf * 16 + g;
                afr[mf][0] = Xs[kk + tg    ][mr    ];
                afr[mf][1] = Xs[kk + tg    ][mr + 8];
                afr[mf][2] = Xs[kk + tg + 4][mr    ];
                afr[mf][3] = Xs[kk + tg + 4][mr + 8];
            }
            #pragma unroll
            for (int nf = 0; nf < NF; nf++) {
                int nr = wn * WSPAN_N + nf * 8;
                uint32_t b0 = Ws[kk + tg    ][nr + g];
                uint32_t b1 = Ws[kk + tg + 4][nr + g];
                #pragma unroll
                for (int mf = 0; mf < MF; mf++) {
                    asm volatile(
                        "mma.sync.aligned.m16n8k8.row.col.f32.tf32.tf32.f32 "
                        "{%0,%1,%2,%3}, {%4,%5,%6,%7}, {%8,%9}, {%0,%1,%2,%3};"
                        : "+f"(acc[mf][nf][0]), "+f"(acc[mf][nf][1]),
                          "+f"(acc[mf][nf][2]), "+f"(acc[mf][nf][3])
                        : "r"(afr[mf][0]), "r"(afr[mf][1]), "r"(afr[mf][2]), "r"(afr[mf][3]),
                          "r"(b0), "r"(b1));
                }
            }
        }
        __syncthreads();
    }

    // epilogue: c0 [g][tg*2], c1 [g][tg*2+1], c2 [g+8][tg*2], c3 [g+8][tg*2+1]
    #pragma unroll
    for (int mf = 0; mf < MF; mf++) {
        int gm0 = rowBase + wm * 32 + mf * 16 + g;
        int gm1 = gm0 + 8;
        #pragma unroll
        for (int nf = 0; nf < NF; nf++) {
            int gj0 = wn * WSPAN_N + nf * 8 + tg * 2;
            int gj1 = gj0 + 1;
            if (gj0 < Nout) {
                float bv = bias[gj0];
                if (gm0 < M) {
                    float v = acc[mf][nf][0] + bv;
                    if (RELU) v = fmaxf(v, 0.f);
                    Y[(size_t)gm0 * Nout + gj0] = v;
                }
                if (gm1 < M) {
                    float v = acc[mf][nf][2] + bv;
                    if (RELU) v = fmaxf(v, 0.f);
                    Y[(size_t)gm1 * Nout + gj0] = v;
                }
            }
            if (gj1 < Nout) {
                float bv = bias[gj1];
                if (gm0 < M) {
                    float v = acc[mf][nf][1] + bv;
                    if (RELU) v = fmaxf(v, 0.f);
                    Y[(size_t)gm0 * Nout + gj1] = v;
                }
                if (gm1 < M) {
                    float v = acc[mf][nf][3] + bv;
                    if (RELU) v = fmaxf(v, 0.f);
                    Y[(size_t)gm1 * Nout + gj1] = v;
                }
            }
        }
    }
}

// ---------------- launch ----------------
extern "C" void kernel_launch(void* const* d_in, const int* in_sizes, int n_in,
                              void* d_out, int out_size) {
    const float* input_feat = (const float*)d_in[0];
    const int*   src = (const int*)d_in[1];
    const int*   dst = (const int*)d_in[2];
    const float* W1  = (const float*)d_in[3];
    const float* b1  = (const float*)d_in[4];
    const float* W2  = (const float*)d_in[5];
    const float* b2  = (const float*)d_in[6];
    const float* Wh1 = (const float*)d_in[7];
    const float* bh1 = (const float*)d_in[8];
    const float* Wh2 = (const float*)d_in[9];
    const float* bh2 = (const float*)d_in[10];

    int n = in_sizes[0] / 64;
    int e = in_sizes[1];
    if (n > NMAX) n = NMAX;
    if (e > EMAX) e = EMAX;

    float* outp = (float*)d_out;

    float4 *fA, *fB, *fC, *h1p, *h2p, *hl_scratch;
    cudaGetSymbolAddress((void**)&fA, g_fA);
    cudaGetSymbolAddress((void**)&fB, g_fB);
    cudaGetSymbolAddress((void**)&fC, g_fC);
    cudaGetSymbolAddress((void**)&h1p, g_h1);
    cudaGetSymbolAddress((void**)&h2p, g_h2);
    cudaGetSymbolAddress((void**)&hl_scratch, g_hlast_scratch);

    float* hlast = (out_size >= n * 168) ? (outp + (size_t)n * 40) : (float*)hl_scratch;

    int nb = (n + 255) / 256;
    int eb = (e + 255) / 256;
    int ntiles = (n + 1023) / 1024;

    k_zero_deg<<<nb, 256>>>(n);
    k_degrees<<<eb, 256>>>(src, dst, e);
    k_norms_tilesum<<<ntiles, 1024>>>(n);
    k_scan_partials<<<1, 128>>>(ntiles);
    k_apply_scan<<<ntiles, 1024>>>(n);
    k_fill<<<eb, 256>>>(src, dst, e);

    int pb = (n + 15) / 16;   // 16 nodes per 256-thread block (half-warp per node)

    // gnn1: feat0 = input_feat, ping-pong fA/fB (ends in fB)
    const float4* f = (const float4*)input_feat;
    const float4* f01 = (const float4*)input_feat;
    for (int s = 0; s < 10; s++) {
        float4* o = (s % 2 == 0) ? fA : fB;
        k_prop<<<pb, 256>>>(f, f01, o, n);
        f = o;
    }
    // gnn2: feat0 = fB (persists), ping-pong fA/fC (ends in fC)
    const float4* f02 = f;
    for (int s = 0; s < 10; s++) {
        float4* o = (s % 2 == 0) ? fA : fC;
        k_prop<<<pb, 256>>>(f, f02, o, n);
        f = o;
    }

    int gridM = (n + 127) / 128;
    k_gemm_tf32<128, true ><<<gridM, 256>>>((const float*)f,   W1,  b1,  (float*)h1p, n, 128,  64);
    k_gemm_tf32<128, false><<<gridM, 256>>>((const float*)h1p, W2,  b2,  hlast,       n, 128, 128);
    k_gemm_tf32< 64, true ><<<gridM, 256>>>(hlast,             Wh1, bh1, (float*)h2p, n,  64, 128);
    k_gemm_tf32< 64, false><<<gridM, 256>>>((const float*)h2p, Wh2, bh2, outp,        n,  40,  64);
}

// round 6
// speedup vs baseline: 1.8044x; 1.0926x over previous
#include <cuda_runtime.h>
#include <math.h>
#include <stdint.h>

#define NMAX 100000
#define EMAX 1000000
#define SAPAD 132

// ---------------- scratch (static device globals; float4-typed => 16B aligned) ----------------
__device__ float4 g_fA[(size_t)NMAX * 16];
__device__ float4 g_fB[(size_t)NMAX * 16];
__device__ float4 g_fC[(size_t)NMAX * 16];
__device__ float4 g_hlast_scratch[(size_t)NMAX * 32];
__device__ int    g_deg_out[NMAX];
__device__ int    g_deg_in[NMAX];
__device__ float  g_snorm[NMAX];
__device__ float  g_dnorm[NMAX];
__device__ int    g_rowptr[NMAX + 1];
__device__ int    g_cursor[NMAX];
__device__ int    g_partials[128];
__device__ int2   g_edges[EMAX];   // .x = src index, .y = bits of 0.9*snorm[src]*dnorm[dst]

// ---------------- graph preprocessing ----------------
__global__ void k_zero_deg(int n) {
    int i = blockIdx.x * blockDim.x + threadIdx.x;
    if (i < n) { g_deg_out[i] = 0; g_deg_in[i] = 0; }
}

__global__ void k_degrees(const int* __restrict__ src, const int* __restrict__ dst, int e) {
    int i = blockIdx.x * blockDim.x + threadIdx.x;
    if (i < e) {
        atomicAdd(&g_deg_out[src[i]], 1);
        atomicAdd(&g_deg_in[dst[i]], 1);
    }
}

__global__ void k_norms_tilesum(int n) {
    int idx = blockIdx.x * 1024 + threadIdx.x;
    int din = 0;
    if (idx < n) {
        int dout = g_deg_out[idx];
        g_snorm[idx] = (dout > 0) ? rsqrtf((float)dout) : 0.f;
        din = g_deg_in[idx];
        g_dnorm[idx] = (din > 0) ? rsqrtf((float)din) : 0.f;
    }
    int v = din;
    #pragma unroll
    for (int o = 16; o; o >>= 1) v += __shfl_down_sync(0xffffffffu, v, o);
    __shared__ int sm[32];
    if ((threadIdx.x & 31) == 0) sm[threadIdx.x >> 5] = v;
    __syncthreads();
    if (threadIdx.x < 32) {
        int s = sm[threadIdx.x];
        #pragma unroll
        for (int o = 16; o; o >>= 1) s += __shfl_down_sync(0xffffffffu, s, o);
        if (threadIdx.x == 0) g_partials[blockIdx.x] = s;
    }
}

__global__ void k_scan_partials(int ntiles) {
    int t = threadIdx.x;
    int v = (t < ntiles) ? g_partials[t] : 0;
    int lane = t & 31, w = t >> 5;
    int x = v;
    #pragma unroll
    for (int o = 1; o < 32; o <<= 1) {
        int y = __shfl_up_sync(0xffffffffu, x, o);
        if (lane >= o) x += y;
    }
    __shared__ int ws[4];
    if (lane == 31) ws[w] = x;
    __syncthreads();
    if (t == 0) {
        int a = 0;
        #pragma unroll
        for (int i = 0; i < 4; i++) { int tmp = ws[i]; ws[i] = a; a += tmp; }
    }
    __syncthreads();
    int excl = x - v + ws[w];
    if (t < ntiles) g_partials[t] = excl;
}

__global__ void k_apply_scan(int n) {
    int tile = blockIdx.x;
    int t = threadIdx.x;
    int idx = tile * 1024 + t;
    int v = (idx < n) ? g_deg_in[idx] : 0;
    int lane = t & 31, w = t >> 5;
    int x = v;
    #pragma unroll
    for (int o = 1; o < 32; o <<= 1) {
        int y = __shfl_up_sync(0xffffffffu, x, o);
        if (lane >= o) x += y;
    }
    __shared__ int ws[32];
    if (lane == 31) ws[w] = x;
    __syncthreads();
    if (t < 32) {
        int y = ws[t];
        #pragma unroll
        for (int o = 1; o < 32; o <<= 1) {
            int z = __shfl_up_sync(0xffffffffu, y, o);
            if (lane >= o) y += z;
        }
        ws[t] = y;
    }
    __syncthreads();
    int winc = (w > 0) ? ws[w - 1] : 0;
    int inc = x + winc + g_partials[tile];
    if (idx < n) {
        g_rowptr[idx + 1] = inc;
        g_cursor[idx] = inc - v;
    }
    if (idx == 0) g_rowptr[0] = 0;
}

__global__ void k_fill(const int* __restrict__ src, const int* __restrict__ dst, int e) {
    int i = blockIdx.x * blockDim.x + threadIdx.x;
    if (i < e) {
        int d = dst[i];
        int s = src[i];
        int p = atomicAdd(&g_cursor[d], 1);
        int2 v;
        v.x = s;
        v.y = __float_as_int(0.9f * g_snorm[s] * g_dnorm[d]);  // fused edge weight
        g_edges[p] = v;
    }
}

// ---------------- APPNP propagation: half-warp/node, float4/lane, 8-edge pipelined ----------------
#define PROP_FMA4(A, W, V) \
    A.x = fmaf(W, V.x, A.x); A.y = fmaf(W, V.y, A.y); \
    A.z = fmaf(W, V.z, A.z); A.w = fmaf(W, V.w, A.w);

__global__ void __launch_bounds__(256) k_prop(
        const float4* __restrict__ fp, const float4* __restrict__ f0,
        float4* __restrict__ fn, int n) {
    int node = blockIdx.x * 16 + (threadIdx.x >> 4);
    if (node >= n) return;
    int lane = threadIdx.x & 15;
    int beg = __ldg(&g_rowptr[node]);
    int end = __ldg(&g_rowptr[node + 1]);

    float4 a0 = make_float4(0.f, 0.f, 0.f, 0.f);
    float4 a1 = make_float4(0.f, 0.f, 0.f, 0.f);

    int e = beg;
    for (; e + 8 <= end; e += 8) {
        int2 e0 = __ldg(&g_edges[e + 0]);
        int2 e1 = __ldg(&g_edges[e + 1]);
        int2 e2 = __ldg(&g_edges[e + 2]);
        int2 e3 = __ldg(&g_edges[e + 3]);
        int2 e4 = __ldg(&g_edges[e + 4]);
        int2 e5 = __ldg(&g_edges[e + 5]);
        int2 e6 = __ldg(&g_edges[e + 6]);
        int2 e7 = __ldg(&g_edges[e + 7]);
        float4 v0 = __ldg(&fp[(size_t)e0.x * 16 + lane]);
        float4 v1 = __ldg(&fp[(size_t)e1.x * 16 + lane]);
        float4 v2 = __ldg(&fp[(size_t)e2.x * 16 + lane]);
        float4 v3 = __ldg(&fp[(size_t)e3.x * 16 + lane]);
        float4 v4 = __ldg(&fp[(size_t)e4.x * 16 + lane]);
        float4 v5 = __ldg(&fp[(size_t)e5.x * 16 + lane]);
        float4 v6 = __ldg(&fp[(size_t)e6.x * 16 + lane]);
        float4 v7 = __ldg(&fp[(size_t)e7.x * 16 + lane]);
        float w0 = __int_as_float(e0.y), w1 = __int_as_float(e1.y);
        float w2 = __int_as_float(e2.y), w3 = __int_as_float(e3.y);
        float w4 = __int_as_float(e4.y), w5 = __int_as_float(e5.y);
        float w6 = __int_as_float(e6.y), w7 = __int_as_float(e7.y);
        PROP_FMA4(a0, w0, v0); PROP_FMA4(a1, w1, v1);
        PROP_FMA4(a0, w2, v2); PROP_FMA4(a1, w3, v3);
        PROP_FMA4(a0, w4, v4); PROP_FMA4(a1, w5, v5);
        PROP_FMA4(a0, w6, v6); PROP_FMA4(a1, w7, v7);
    }
    for (; e + 4 <= end; e += 4) {
        int2 e0 = __ldg(&g_edges[e + 0]);
        int2 e1 = __ldg(&g_edges[e + 1]);
        int2 e2 = __ldg(&g_edges[e + 2]);
        int2 e3 = __ldg(&g_edges[e + 3]);
        float4 v0 = __ldg(&fp[(size_t)e0.x * 16 + lane]);
        float4 v1 = __ldg(&fp[(size_t)e1.x * 16 + lane]);
        float4 v2 = __ldg(&fp[(size_t)e2.x * 16 + lane]);
        float4 v3 = __ldg(&fp[(size_t)e3.x * 16 + lane]);
        float w0 = __int_as_float(e0.y), w1 = __int_as_float(e1.y);
        float w2 = __int_as_float(e2.y), w3 = __int_as_float(e3.y);
        PROP_FMA4(a0, w0, v0); PROP_FMA4(a1, w1, v1);
        PROP_FMA4(a0, w2, v2); PROP_FMA4(a1, w3, v3);
    }
    for (; e < end; e++) {
        int2 ev = __ldg(&g_edges[e]);
        float w = __int_as_float(ev.y);
        float4 v = __ldg(&fp[(size_t)ev.x * 16 + lane]);
        PROP_FMA4(a0, w, v);
    }
    float ax = a0.x + a1.x, ay = a0.y + a1.y;
    float az = a0.z + a1.z, aw = a0.w + a1.w;

    float4 b = __ldg(&f0[(size_t)node * 16 + lane]);
    float4 o;
    o.x = fmaf(0.1f, b.x, ax);
    o.y = fmaf(0.1f, b.y, ay);
    o.z = fmaf(0.1f, b.z, az);
    o.w = fmaf(0.1f, b.w, aw);
    fn[(size_t)node * 16 + lane] = o;
}

// ---------------- fused tf32 MLP: out = relu(relu(X W1+b1) W2+b2 ... ) ----------------
__device__ __forceinline__ uint32_t f2tf32(float v) {
    uint32_t u;
    asm("cvt.rna.tf32.f32 %0, %1;" : "=r"(u) : "f"(v));
    return u;
}

// mma over sA [k][m] x sW [k][n]; 8 warps 4(M)x2(N); MF=2 (32 rows/warp).
template<int K, int NF>
__device__ __forceinline__ void mma_stage(
        const uint32_t* __restrict__ sA, const uint32_t* __restrict__ sW,
        int wm, int wn, int g, int tg, float (&acc)[2][8][4]) {
    #pragma unroll
    for (int kk = 0; kk < K; kk += 8) {
        uint32_t afr[2][4];
        #pragma unroll
        for (int mf = 0; mf < 2; mf++) {
            int mr = wm * 32 + mf * 16 + g;
            afr[mf][0] = sA[(kk + tg    ) * SAPAD + mr    ];
            afr[mf][1] = sA[(kk + tg    ) * SAPAD + mr + 8];
            afr[mf][2] = sA[(kk + tg + 4) * SAPAD + mr    ];
            afr[mf][3] = sA[(kk + tg + 4) * SAPAD + mr + 8];
        }
        #pragma unroll
        for (int nf = 0; nf < NF; nf++) {
            int nr = wn * NF * 8 + nf * 8 + g;
            uint32_t b0 = sW[(kk + tg    ) * SAPAD + nr];
            uint32_t b1 = sW[(kk + tg + 4) * SAPAD + nr];
            #pragma unroll
            for (int mf = 0; mf < 2; mf++) {
                asm volatile(
                    "mma.sync.aligned.m16n8k8.row.col.f32.tf32.tf32.f32 "
                    "{%0,%1,%2,%3}, {%4,%5,%6,%7}, {%8,%9}, {%0,%1,%2,%3};"
                    : "+f"(acc[mf][nf][0]), "+f"(acc[mf][nf][1]),
                      "+f"(acc[mf][nf][2]), "+f"(acc[mf][nf][3])
                    : "r"(afr[mf][0]), "r"(afr[mf][1]), "r"(afr[mf][2]), "r"(afr[mf][3]),
                      "r"(b0), "r"(b1));
            }
        }
    }
}

__device__ __forceinline__ void zero_acc(float (&acc)[2][8][4]) {
    #pragma unroll
    for (int i = 0; i < 2; i++)
        #pragma unroll
        for (int j = 0; j < 8; j++)
            #pragma unroll
            for (int r = 0; r < 4; r++) acc[i][j][r] = 0.f;
}

// store acc (+bias, opt relu) into sA transposed [k=col][m=row] and/or gmem
template<int NF, bool RELU, bool TO_SA, bool TO_GM>
__device__ __forceinline__ void store_acts(
        float (&acc)[2][8][4], const float* __restrict__ bias,
        uint32_t* __restrict__ sA, int wm, int wn, int g, int tg,
        float* __restrict__ gm_out, int gm_cols, int col_limit,
        int rowBase, int M) {
    #pragma unroll
    for (int mf = 0; mf < 2; mf++) {
        int r0 = wm * 32 + mf * 16 + g, r1 = r0 + 8;
        #pragma unroll
        for (int nf = 0; nf < NF; nf++) {
            int c0 = wn * NF * 8 + nf * 8 + tg * 2, c1 = c0 + 1;
            float bv0 = (c0 < col_limit) ? bias[c0] : 0.f;
            float bv1 = (c1 < col_limit) ? bias[c1] : 0.f;
            float v00 = acc[mf][nf][0] + bv0;
            float v01 = acc[mf][nf][1] + bv1;
            float v10 = acc[mf][nf][2] + bv0;
            float v11 = acc[mf][nf][3] + bv1;
            if (RELU) {
                v00 = fmaxf(v00, 0.f); v01 = fmaxf(v01, 0.f);
                v10 = fmaxf(v10, 0.f); v11 = fmaxf(v11, 0.f);
            }
            if (TO_SA) {
                sA[c0 * SAPAD + r0] = f2tf32(v00);
                sA[c1 * SAPAD + r0] = f2tf32(v01);
                sA[c0 * SAPAD + r1] = f2tf32(v10);
                sA[c1 * SAPAD + r1] = f2tf32(v11);
            }
            if (TO_GM) {
                int gr0 = rowBase + r0, gr1 = rowBase + r1;
                if (gr0 < M) {
                    if (c0 < col_limit) gm_out[(size_t)gr0 * gm_cols + c0] = v00;
                    if (c1 < col_limit) gm_out[(size_t)gr0 * gm_cols + c1] = v01;
                }
                if (gr1 < M) {
                    if (c0 < col_limit) gm_out[(size_t)gr1 * gm_cols + c0] = v10;
                    if (c1 < col_limit) gm_out[(size_t)gr1 * gm_cols + c1] = v11;
                }
            }
        }
    }
}

__global__ void __launch_bounds__(256) k_mlp(
        const float* __restrict__ X,
        const float* __restrict__ W1,  const float* __restrict__ b1,
        const float* __restrict__ W2,  const float* __restrict__ b2,
        const float* __restrict__ Wh1, const float* __restrict__ bh1,
        const float* __restrict__ Wh2, const float* __restrict__ bh2,
        float* __restrict__ hlast, float* __restrict__ out, int M) {
    extern __shared__ uint32_t sh[];
    uint32_t* sA = sh;                  // [128][SAPAD] activations, k-major
    uint32_t* sW = sh + 128 * SAPAD;    // [128][SAPAD] weights, k-major

    int tid = threadIdx.x;
    int wid = tid >> 5, lane = tid & 31;
    int g = lane >> 2, tg = lane & 3;
    int wm = wid & 3, wn = wid >> 2;
    int rowBase = blockIdx.x * 128;

    // load X (M-tile x 64) -> sA[k][m]
    #pragma unroll
    for (int i = tid; i < 128 * 16; i += 256) {
        int m = i / 16, kq = i % 16;
        float4 v = make_float4(0.f, 0.f, 0.f, 0.f);
        int gm = rowBase + m;
        if (gm < M) v = *reinterpret_cast<const float4*>(&X[(size_t)gm * 64 + kq * 4]);
        sA[(kq * 4 + 0) * SAPAD + m] = f2tf32(v.x);
        sA[(kq * 4 + 1) * SAPAD + m] = f2tf32(v.y);
        sA[(kq * 4 + 2) * SAPAD + m] = f2tf32(v.z);
        sA[(kq * 4 + 3) * SAPAD + m] = f2tf32(v.w);
    }
    // load W1 (64 x 128) -> sW[k][n]
    #pragma unroll
    for (int i = tid; i < 64 * 32; i += 256) {
        int k = i / 32, nq = i % 32;
        float4 v = *reinterpret_cast<const float4*>(&W1[(size_t)k * 128 + nq * 4]);
        sW[k * SAPAD + nq * 4 + 0] = f2tf32(v.x);
        sW[k * SAPAD + nq * 4 + 1] = f2tf32(v.y);
        sW[k * SAPAD + nq * 4 + 2] = f2tf32(v.z);
        sW[k * SAPAD + nq * 4 + 3] = f2tf32(v.w);
    }
    __syncthreads();

    float acc[2][8][4];

    // ---- stage 1: h1 = relu(X W1 + b1), K=64, N=128
    zero_acc(acc);
    mma_stage<64, 8>(sA, sW, wm, wn, g, tg, acc);
    __syncthreads();
    store_acts<8, true, true, false>(acc, b1, sA, wm, wn, g, tg, nullptr, 0, 128, rowBase, M);
    // load W2 (128 x 128)
    #pragma unroll
    for (int i = tid; i < 128 * 32; i += 256) {
        int k = i / 32, nq = i % 32;
        float4 v = *reinterpret_cast<const float4*>(&W2[(size_t)k * 128 + nq * 4]);
        sW[k * SAPAD + nq * 4 + 0] = f2tf32(v.x);
        sW[k * SAPAD + nq * 4 + 1] = f2tf32(v.y);
        sW[k * SAPAD + nq * 4 + 2] = f2tf32(v.z);
        sW[k * SAPAD + nq * 4 + 3] = f2tf32(v.w);
    }
    __syncthreads();

    // ---- stage 2: hlast = h1 W2 + b2, K=128, N=128 (also to gmem)
    zero_acc(acc);
    mma_stage<128, 8>(sA, sW, wm, wn, g, tg, acc);
    __syncthreads();
    store_acts<8, false, true, true>(acc, b2, sA, wm, wn, g, tg, hlast, 128, 128, rowBase, M);
    // load Wh1 (128 x 64)
    #pragma unroll
    for (int i = tid; i < 128 * 16; i += 256) {
        int k = i / 16, nq = i % 16;
        float4 v = *reinterpret_cast<const float4*>(&Wh1[(size_t)k * 64 + nq * 4]);
        sW[k * SAPAD + nq * 4 + 0] = f2tf32(v.x);
        sW[k * SAPAD + nq * 4 + 1] = f2tf32(v.y);
        sW[k * SAPAD + nq * 4 + 2] = f2tf32(v.z);
        sW[k * SAPAD + nq * 4 + 3] = f2tf32(v.w);
    }
    __syncthreads();

    // ---- stage 3: h2 = relu(hlast Wh1 + bh1), K=128, N=64
    zero_acc(acc);
    mma_stage<128, 4>(sA, sW, wm, wn, g, tg, acc);
    __syncthreads();
    store_acts<4, true, true, false>(acc, bh1, sA, wm, wn, g, tg, nullptr, 0, 64, rowBase, M);
    // load Wh2 (64 x 40, zero-padded to 64 cols)
    #pragma unroll
    for (int i = tid; i < 64 * 64; i += 256) {
        int k = i / 64, j = i % 64;
        float v = (j < 40) ? Wh2[(size_t)k * 40 + j] : 0.f;
        sW[k * SAPAD + j] = f2tf32(v);
    }
    __syncthreads();

    // ---- stage 4: out = h2 Wh2 + bh2, K=64, N=40 (padded 64)
    zero_acc(acc);
    mma_stage<64, 4>(sA, sW, wm, wn, g, tg, acc);
    __syncthreads();
    store_acts<4, false, false, true>(acc, bh2, nullptr, wm, wn, g, tg, out, 40, 40, rowBase, M);
}

// ---------------- launch ----------------
extern "C" void kernel_launch(void* const* d_in, const int* in_sizes, int n_in,
                              void* d_out, int out_size) {
    const float* input_feat = (const float*)d_in[0];
    const int*   src = (const int*)d_in[1];
    const int*   dst = (const int*)d_in[2];
    const float* W1  = (const float*)d_in[3];
    const float* b1  = (const float*)d_in[4];
    const float* W2  = (const float*)d_in[5];
    const float* b2  = (const float*)d_in[6];
    const float* Wh1 = (const float*)d_in[7];
    const float* bh1 = (const float*)d_in[8];
    const float* Wh2 = (const float*)d_in[9];
    const float* bh2 = (const float*)d_in[10];

    int n = in_sizes[0] / 64;
    int e = in_sizes[1];
    if (n > NMAX) n = NMAX;
    if (e > EMAX) e = EMAX;

    float* outp = (float*)d_out;

    float4 *fA, *fB, *fC, *hl_scratch;
    cudaGetSymbolAddress((void**)&fA, g_fA);
    cudaGetSymbolAddress((void**)&fB, g_fB);
    cudaGetSymbolAddress((void**)&fC, g_fC);
    cudaGetSymbolAddress((void**)&hl_scratch, g_hlast_scratch);

    float* hlast = (out_size >= n * 168) ? (outp + (size_t)n * 40) : (float*)hl_scratch;

    int nb = (n + 255) / 256;
    int eb = (e + 255) / 256;
    int ntiles = (n + 1023) / 1024;

    k_zero_deg<<<nb, 256>>>(n);
    k_degrees<<<eb, 256>>>(src, dst, e);
    k_norms_tilesum<<<ntiles, 1024>>>(n);
    k_scan_partials<<<1, 128>>>(ntiles);
    k_apply_scan<<<ntiles, 1024>>>(n);
    k_fill<<<eb, 256>>>(src, dst, e);

    int pb = (n + 15) / 16;

    // gnn1: feat0 = input_feat, ping-pong fA/fB (ends in fB)
    const float4* f = (const float4*)input_feat;
    const float4* f01 = (const float4*)input_feat;
    for (int s = 0; s < 10; s++) {
        float4* o = (s % 2 == 0) ? fA : fB;
        k_prop<<<pb, 256>>>(f, f01, o, n);
        f = o;
    }
    // gnn2: feat0 = fB (persists), ping-pong fA/fC (ends in fC)
    const float4* f02 = f;
    for (int s = 0; s < 10; s++) {
        float4* o = (s % 2 == 0) ? fA : fC;
        k_prop<<<pb, 256>>>(f, f02, o, n);
        f = o;
    }

    // fused MLP: one kernel, activations resident in SMEM
    const int MLP_SMEM = 2 * 128 * SAPAD * 4;   // 135168 B
    cudaFuncSetAttribute(k_mlp, cudaFuncAttributeMaxDynamicSharedMemorySize, MLP_SMEM);
    int gridM = (n + 127) / 128;
    k_mlp<<<gridM, 256, MLP_SMEM>>>((const float*)f, W1, b1, W2, b2,
                                    Wh1, bh1, Wh2, bh2, hlast, outp, n);
}

// round 7
// speedup vs baseline: 2.1126x; 1.1708x over previous
#include <cuda_runtime.h>
#include <math.h>
#include <stdint.h>

#define NMAX 100000
#define EMAX 1000000
#define SAPAD 132

// ---------------- scratch (static device globals; float4-typed => 16B aligned) ----------------
__device__ float4 g_fA[(size_t)NMAX * 16];
__device__ float4 g_fB[(size_t)NMAX * 16];
__device__ float4 g_fC[(size_t)NMAX * 16];
__device__ float4 g_hlast_scratch[(size_t)NMAX * 32];
__device__ int    g_deg_out[NMAX];
__device__ int    g_deg_in[NMAX];
__device__ float  g_snorm[NMAX];
__device__ float  g_dnorm[NMAX];
__device__ int    g_rowptr[NMAX + 1];
__device__ int    g_cursor[NMAX];
__device__ int    g_partials[128];
__device__ int2   g_edges[EMAX];   // .x = src index, .y = bits of 0.9*snorm[src]*dnorm[dst]

// ---------------- graph preprocessing ----------------
__global__ void k_zero_deg(int n) {
    int i = blockIdx.x * blockDim.x + threadIdx.x;
    if (i < n) { g_deg_out[i] = 0; g_deg_in[i] = 0; }
}

__global__ void k_degrees(const int* __restrict__ src, const int* __restrict__ dst, int e) {
    int i = blockIdx.x * blockDim.x + threadIdx.x;
    if (i < e) {
        atomicAdd(&g_deg_out[src[i]], 1);
        atomicAdd(&g_deg_in[dst[i]], 1);
    }
}

__global__ void k_norms_tilesum(int n) {
    int idx = blockIdx.x * 1024 + threadIdx.x;
    int din = 0;
    if (idx < n) {
        int dout = g_deg_out[idx];
        g_snorm[idx] = (dout > 0) ? rsqrtf((float)dout) : 0.f;
        din = g_deg_in[idx];
        g_dnorm[idx] = (din > 0) ? rsqrtf((float)din) : 0.f;
    }
    int v = din;
    #pragma unroll
    for (int o = 16; o; o >>= 1) v += __shfl_down_sync(0xffffffffu, v, o);
    __shared__ int sm[32];
    if ((threadIdx.x & 31) == 0) sm[threadIdx.x >> 5] = v;
    __syncthreads();
    if (threadIdx.x < 32) {
        int s = sm[threadIdx.x];
        #pragma unroll
        for (int o = 16; o; o >>= 1) s += __shfl_down_sync(0xffffffffu, s, o);
        if (threadIdx.x == 0) g_partials[blockIdx.x] = s;
    }
}

__global__ void k_scan_partials(int ntiles) {
    int t = threadIdx.x;
    int v = (t < ntiles) ? g_partials[t] : 0;
    int lane = t & 31, w = t >> 5;
    int x = v;
    #pragma unroll
    for (int o = 1; o < 32; o <<= 1) {
        int y = __shfl_up_sync(0xffffffffu, x, o);
        if (lane >= o) x += y;
    }
    __shared__ int ws[4];
    if (lane == 31) ws[w] = x;
    __syncthreads();
    if (t == 0) {
        int a = 0;
        #pragma unroll
        for (int i = 0; i < 4; i++) { int tmp = ws[i]; ws[i] = a; a += tmp; }
    }
    __syncthreads();
    int excl = x - v + ws[w];
    if (t < ntiles) g_partials[t] = excl;
}

__global__ void k_apply_scan(int n) {
    int tile = blockIdx.x;
    int t = threadIdx.x;
    int idx = tile * 1024 + t;
    int v = (idx < n) ? g_deg_in[idx] : 0;
    int lane = t & 31, w = t >> 5;
    int x = v;
    #pragma unroll
    for (int o = 1; o < 32; o <<= 1) {
        int y = __shfl_up_sync(0xffffffffu, x, o);
        if (lane >= o) x += y;
    }
    __shared__ int ws[32];
    if (lane == 31) ws[w] = x;
    __syncthreads();
    if (t < 32) {
        int y = ws[t];
        #pragma unroll
        for (int o = 1; o < 32; o <<= 1) {
            int z = __shfl_up_sync(0xffffffffu, y, o);
            if (lane >= o) y += z;
        }
        ws[t] = y;
    }
    __syncthreads();
    int winc = (w > 0) ? ws[w - 1] : 0;
    int inc = x + winc + g_partials[tile];
    if (idx < n) {
        g_rowptr[idx + 1] = inc;
        g_cursor[idx] = inc - v;
    }
    if (idx == 0) g_rowptr[0] = 0;
}

__global__ void k_fill(const int* __restrict__ src, const int* __restrict__ dst, int e) {
    int i = blockIdx.x * blockDim.x + threadIdx.x;
    if (i < e) {
        int d = dst[i];
        int s = src[i];
        int p = atomicAdd(&g_cursor[d], 1);
        int2 v;
        v.x = s;
        v.y = __float_as_int(0.9f * g_snorm[s] * g_dnorm[d]);  // fused edge weight
        g_edges[p] = v;
    }
}

// ---------------- APPNP propagation: grid-stride, half-warp/node, 4-edge pipelined ----------------
#define PROP_FMA4(A, W, V) \
    A.x = fmaf(W, V.x, A.x); A.y = fmaf(W, V.y, A.y); \
    A.z = fmaf(W, V.z, A.z); A.w = fmaf(W, V.w, A.w);

__global__ void __launch_bounds__(256, 6) k_prop(
        const float4* __restrict__ fp, const float4* __restrict__ f0,
        float4* __restrict__ fn, int n) {
    int lane = threadIdx.x & 15;
    int hw0 = blockIdx.x * 16 + (threadIdx.x >> 4);
    int stride = gridDim.x * 16;

    for (int node = hw0; node < n; node += stride) {
        int beg = __ldg(&g_rowptr[node]);
        int end = __ldg(&g_rowptr[node + 1]);

        float4 a0 = make_float4(0.f, 0.f, 0.f, 0.f);
        float4 a1 = make_float4(0.f, 0.f, 0.f, 0.f);

        int e = beg;
        for (; e + 4 <= end; e += 4) {
            int2 e0 = __ldg(&g_edges[e + 0]);
            int2 e1 = __ldg(&g_edges[e + 1]);
            int2 e2 = __ldg(&g_edges[e + 2]);
            int2 e3 = __ldg(&g_edges[e + 3]);
            float4 v0 = __ldg(&fp[(size_t)e0.x * 16 + lane]);
            float4 v1 = __ldg(&fp[(size_t)e1.x * 16 + lane]);
            float4 v2 = __ldg(&fp[(size_t)e2.x * 16 + lane]);
            float4 v3 = __ldg(&fp[(size_t)e3.x * 16 + lane]);
            float w0 = __int_as_float(e0.y), w1 = __int_as_float(e1.y);
            float w2 = __int_as_float(e2.y), w3 = __int_as_float(e3.y);
            PROP_FMA4(a0, w0, v0); PROP_FMA4(a1, w1, v1);
            PROP_FMA4(a0, w2, v2); PROP_FMA4(a1, w3, v3);
        }
        if (e + 2 <= end) {
            int2 e0 = __ldg(&g_edges[e + 0]);
            int2 e1 = __ldg(&g_edges[e + 1]);
            float4 v0 = __ldg(&fp[(size_t)e0.x * 16 + lane]);
            float4 v1 = __ldg(&fp[(size_t)e1.x * 16 + lane]);
            float w0 = __int_as_float(e0.y), w1 = __int_as_float(e1.y);
            PROP_FMA4(a0, w0, v0); PROP_FMA4(a1, w1, v1);
            e += 2;
        }
        if (e < end) {
            int2 ev = __ldg(&g_edges[e]);
            float w = __int_as_float(ev.y);
            float4 v = __ldg(&fp[(size_t)ev.x * 16 + lane]);
            PROP_FMA4(a0, w, v);
        }
        float ax = a0.x + a1.x, ay = a0.y + a1.y;
        float az = a0.z + a1.z, aw = a0.w + a1.w;

        float4 b = __ldg(&f0[(size_t)node * 16 + lane]);
        float4 o;
        o.x = fmaf(0.1f, b.x, ax);
        o.y = fmaf(0.1f, b.y, ay);
        o.z = fmaf(0.1f, b.z, az);
        o.w = fmaf(0.1f, b.w, aw);
        fn[(size_t)node * 16 + lane] = o;
    }
}

// ---------------- fused tf32 MLP ----------------
__device__ __forceinline__ uint32_t f2tf32(float v) {
    uint32_t u;
    asm("cvt.rna.tf32.f32 %0, %1;" : "=r"(u) : "f"(v));
    return u;
}

template<int K, int NF>
__device__ __forceinline__ void mma_stage(
        const uint32_t* __restrict__ sA, const uint32_t* __restrict__ sW,
        int wm, int wn, int g, int tg, float (&acc)[2][8][4]) {
    #pragma unroll
    for (int kk = 0; kk < K; kk += 8) {
        uint32_t afr[2][4];
        #pragma unroll
        for (int mf = 0; mf < 2; mf++) {
            int mr = wm * 32 + mf * 16 + g;
            afr[mf][0] = sA[(kk + tg    ) * SAPAD + mr    ];
            afr[mf][1] = sA[(kk + tg    ) * SAPAD + mr + 8];
            afr[mf][2] = sA[(kk + tg + 4) * SAPAD + mr    ];
            afr[mf][3] = sA[(kk + tg + 4) * SAPAD + mr + 8];
        }
        #pragma unroll
        for (int nf = 0; nf < NF; nf++) {
            int nr = wn * NF * 8 + nf * 8 + g;
            uint32_t b0 = sW[(kk + tg    ) * SAPAD + nr];
            uint32_t b1 = sW[(kk + tg + 4) * SAPAD + nr];
            #pragma unroll
            for (int mf = 0; mf < 2; mf++) {
                asm volatile(
                    "mma.sync.aligned.m16n8k8.row.col.f32.tf32.tf32.f32 "
                    "{%0,%1,%2,%3}, {%4,%5,%6,%7}, {%8,%9}, {%0,%1,%2,%3};"
                    : "+f"(acc[mf][nf][0]), "+f"(acc[mf][nf][1]),
                      "+f"(acc[mf][nf][2]), "+f"(acc[mf][nf][3])
                    : "r"(afr[mf][0]), "r"(afr[mf][1]), "r"(afr[mf][2]), "r"(afr[mf][3]),
                      "r"(b0), "r"(b1));
            }
        }
    }
}

__device__ __forceinline__ void zero_acc(float (&acc)[2][8][4]) {
    #pragma unroll
    for (int i = 0; i < 2; i++)
        #pragma unroll
        for (int j = 0; j < 8; j++)
            #pragma unroll
            for (int r = 0; r < 4; r++) acc[i][j][r] = 0.f;
}

template<int NF, bool RELU, bool TO_SA, bool TO_GM>
__device__ __forceinline__ void store_acts(
        float (&acc)[2][8][4], const float* __restrict__ bias,
        uint32_t* __restrict__ sA, int wm, int wn, int g, int tg,
        float* __restrict__ gm_out, int gm_cols, int col_limit,
        int rowBase, int M) {
    #pragma unroll
    for (int mf = 0; mf < 2; mf++) {
        int r0 = wm * 32 + mf * 16 + g, r1 = r0 + 8;
        #pragma unroll
        for (int nf = 0; nf < NF; nf++) {
            int c0 = wn * NF * 8 + nf * 8 + tg * 2, c1 = c0 + 1;
            float bv0 = (c0 < col_limit) ? bias[c0] : 0.f;
            float bv1 = (c1 < col_limit) ? bias[c1] : 0.f;
            float v00 = acc[mf][nf][0] + bv0;
            float v01 = acc[mf][nf][1] + bv1;
            float v10 = acc[mf][nf][2] + bv0;
            float v11 = acc[mf][nf][3] + bv1;
            if (RELU) {
                v00 = fmaxf(v00, 0.f); v01 = fmaxf(v01, 0.f);
                v10 = fmaxf(v10, 0.f); v11 = fmaxf(v11, 0.f);
            }
            if (TO_SA) {
                sA[c0 * SAPAD + r0] = f2tf32(v00);
                sA[c1 * SAPAD + r0] = f2tf32(v01);
                sA[c0 * SAPAD + r1] = f2tf32(v10);
                sA[c1 * SAPAD + r1] = f2tf32(v11);
            }
            if (TO_GM) {
                int gr0 = rowBase + r0, gr1 = rowBase + r1;
                if (gr0 < M) {
                    if (c0 < col_limit) gm_out[(size_t)gr0 * gm_cols + c0] = v00;
                    if (c1 < col_limit) gm_out[(size_t)gr0 * gm_cols + c1] = v01;
                }
                if (gr1 < M) {
                    if (c0 < col_limit) gm_out[(size_t)gr1 * gm_cols + c0] = v10;
                    if (c1 < col_limit) gm_out[(size_t)gr1 * gm_cols + c1] = v11;
                }
            }
        }
    }
}

__global__ void __launch_bounds__(256) k_mlp(
        const float* __restrict__ X,
        const float* __restrict__ W1,  const float* __restrict__ b1,
        const float* __restrict__ W2,  const float* __restrict__ b2,
        const float* __restrict__ Wh1, const float* __restrict__ bh1,
        const float* __restrict__ Wh2, const float* __restrict__ bh2,
        float* __restrict__ hlast, float* __restrict__ out, int M) {
    extern __shared__ uint32_t sh[];
    uint32_t* sA = sh;
    uint32_t* sW = sh + 128 * SAPAD;

    int tid = threadIdx.x;
    int wid = tid >> 5, lane = tid & 31;
    int g = lane >> 2, tg = lane & 3;
    int wm = wid & 3, wn = wid >> 2;
    int rowBase = blockIdx.x * 128;

    #pragma unroll
    for (int i = tid; i < 128 * 16; i += 256) {
        int m = i / 16, kq = i % 16;
        float4 v = make_float4(0.f, 0.f, 0.f, 0.f);
        int gm = rowBase + m;
        if (gm < M) v = *reinterpret_cast<const float4*>(&X[(size_t)gm * 64 + kq * 4]);
        sA[(kq * 4 + 0) * SAPAD + m] = f2tf32(v.x);
        sA[(kq * 4 + 1) * SAPAD + m] = f2tf32(v.y);
        sA[(kq * 4 + 2) * SAPAD + m] = f2tf32(v.z);
        sA[(kq * 4 + 3) * SAPAD + m] = f2tf32(v.w);
    }
    #pragma unroll
    for (int i = tid; i < 64 * 32; i += 256) {
        int k = i / 32, nq = i % 32;
        float4 v = *reinterpret_cast<const float4*>(&W1[(size_t)k * 128 + nq * 4]);
        sW[k * SAPAD + nq * 4 + 0] = f2tf32(v.x);
        sW[k * SAPAD + nq * 4 + 1] = f2tf32(v.y);
        sW[k * SAPAD + nq * 4 + 2] = f2tf32(v.z);
        sW[k * SAPAD + nq * 4 + 3] = f2tf32(v.w);
    }
    __syncthreads();

    float acc[2][8][4];

    zero_acc(acc);
    mma_stage<64, 8>(sA, sW, wm, wn, g, tg, acc);
    __syncthreads();
    store_acts<8, true, true, false>(acc, b1, sA, wm, wn, g, tg, nullptr, 0, 128, rowBase, M);
    #pragma unroll
    for (int i = tid; i < 128 * 32; i += 256) {
        int k = i / 32, nq = i % 32;
        float4 v = *reinterpret_cast<const float4*>(&W2[(size_t)k * 128 + nq * 4]);
        sW[k * SAPAD + nq * 4 + 0] = f2tf32(v.x);
        sW[k * SAPAD + nq * 4 + 1] = f2tf32(v.y);
        sW[k * SAPAD + nq * 4 + 2] = f2tf32(v.z);
        sW[k * SAPAD + nq * 4 + 3] = f2tf32(v.w);
    }
    __syncthreads();

    zero_acc(acc);
    mma_stage<128, 8>(sA, sW, wm, wn, g, tg, acc);
    __syncthreads();
    store_acts<8, false, true, true>(acc, b2, sA, wm, wn, g, tg, hlast, 128, 128, rowBase, M);
    #pragma unroll
    for (int i = tid; i < 128 * 16; i += 256) {
        int k = i / 16, nq = i % 16;
        float4 v = *reinterpret_cast<const float4*>(&Wh1[(size_t)k * 64 + nq * 4]);
        sW[k * SAPAD + nq * 4 + 0] = f2tf32(v.x);
        sW[k * SAPAD + nq * 4 + 1] = f2tf32(v.y);
        sW[k * SAPAD + nq * 4 + 2] = f2tf32(v.z);
        sW[k * SAPAD + nq * 4 + 3] = f2tf32(v.w);
    }
    __syncthreads();

    zero_acc(acc);
    mma_stage<128, 4>(sA, sW, wm, wn, g, tg, acc);
    __syncthreads();
    store_acts<4, true, true, false>(acc, bh1, sA, wm, wn, g, tg, nullptr, 0, 64, rowBase, M);
    #pragma unroll
    for (int i = tid; i < 64 * 64; i += 256) {
        int k = i / 64, j = i % 64;
        float v = (j < 40) ? Wh2[(size_t)k * 40 + j] : 0.f;
        sW[k * SAPAD + j] = f2tf32(v);
    }
    __syncthreads();

    zero_acc(acc);
    mma_stage<64, 4>(sA, sW, wm, wn, g, tg, acc);
    __syncthreads();
    store_acts<4, false, false, true>(acc, bh2, nullptr, wm, wn, g, tg, out, 40, 40, rowBase, M);
}

// ---------------- launch ----------------
extern "C" void kernel_launch(void* const* d_in, const int* in_sizes, int n_in,
                              void* d_out, int out_size) {
    const float* input_feat = (const float*)d_in[0];
    const int*   src = (const int*)d_in[1];
    const int*   dst = (const int*)d_in[2];
    const float* W1  = (const float*)d_in[3];
    const float* b1  = (const float*)d_in[4];
    const float* W2  = (const float*)d_in[5];
    const float* b2  = (const float*)d_in[6];
    const float* Wh1 = (const float*)d_in[7];
    const float* bh1 = (const float*)d_in[8];
    const float* Wh2 = (const float*)d_in[9];
    const float* bh2 = (const float*)d_in[10];

    int n = in_sizes[0] / 64;
    int e = in_sizes[1];
    if (n > NMAX) n = NMAX;
    if (e > EMAX) e = EMAX;

    float* outp = (float*)d_out;

    float4 *fA, *fB, *fC, *hl_scratch;
    cudaGetSymbolAddress((void**)&fA, g_fA);
    cudaGetSymbolAddress((void**)&fB, g_fB);
    cudaGetSymbolAddress((void**)&fC, g_fC);
    cudaGetSymbolAddress((void**)&hl_scratch, g_hlast_scratch);

    float* hlast = (out_size >= n * 168) ? (outp + (size_t)n * 40) : (float*)hl_scratch;

    int nb = (n + 255) / 256;
    int eb = (e + 255) / 256;
    int ntiles = (n + 1023) / 1024;

    k_zero_deg<<<nb, 256>>>(n);
    k_degrees<<<eb, 256>>>(src, dst, e);
    k_norms_tilesum<<<ntiles, 1024>>>(n);
    k_scan_partials<<<1, 128>>>(ntiles);
    k_apply_scan<<<ntiles, 1024>>>(n);
    k_fill<<<eb, 256>>>(src, dst, e);

    // grid-stride persistent-shape prop: 6 blocks/SM, single wave
    int dev = 0, smCount = 148;
    cudaGetDevice(&dev);
    cudaDeviceGetAttribute(&smCount, cudaDevAttrMultiProcessorCount, dev);
    int pbMax = (n + 15) / 16;
    int pb = smCount * 6;
    if (pb > pbMax) pb = pbMax;

    // gnn1: feat0 = input_feat, ping-pong fA/fB (ends in fB)
    const float4* f = (const float4*)input_feat;
    const float4* f01 = (const float4*)input_feat;
    for (int s = 0; s < 10; s++) {
        float4* o = (s % 2 == 0) ? fA : fB;
        k_prop<<<pb, 256>>>(f, f01, o, n);
        f = o;
    }
    // gnn2: feat0 = fB (persists), ping-pong fA/fC (ends in fC)
    const float4* f02 = f;
    for (int s = 0; s < 10; s++) {
        float4* o = (s % 2 == 0) ? fA : fC;
        k_prop<<<pb, 256>>>(f, f02, o, n);
        f = o;
    }

    // fused MLP: one kernel, activations resident in SMEM
    const int MLP_SMEM = 2 * 128 * SAPAD * 4;   // 135168 B
    cudaFuncSetAttribute(k_mlp, cudaFuncAttributeMaxDynamicSharedMemorySize, MLP_SMEM);
    int gridM = (n + 127) / 128;
    k_mlp<<<gridM, 256, MLP_SMEM>>>((const float*)f, W1, b1, W2, b2,
                                    Wh1, bh1, Wh2, bh2, hlast, outp, n);
}

// round 9
// speedup vs baseline: 2.8935x; 1.3696x over previous
#include <cuda_runtime.h>
#include <cuda_fp16.h>
#include <math.h>
#include <stdint.h>

#define NMAX 100000
#define EMAX 1000000
#define SAPAD 132

// ---------------- half2 <-> u32 bit casts (no nonstandard intrinsics) ----------------
__device__ __forceinline__ uint32_t h2_bits(__half2 h) {
    return *reinterpret_cast<uint32_t*>(&h);
}
__device__ __forceinline__ __half2 bits_h2(uint32_t u) {
    return *reinterpret_cast<__half2*>(&u);
}

// ---------------- scratch (static device globals) ----------------
// fp16 feature buffers: one row = 64 halves = 128 B = 8 uint4
__device__ uint4  g_h0[(size_t)NMAX * 8];
__device__ uint4  g_hA[(size_t)NMAX * 8];
__device__ uint4  g_hB[(size_t)NMAX * 8];
__device__ uint4  g_hC[(size_t)NMAX * 8];
__device__ float4 g_f32out[(size_t)NMAX * 16];    // final prop output, fp32 (MLP input)
__device__ float4 g_hlast_scratch[(size_t)NMAX * 32];
__device__ int    g_deg_out[NMAX];
__device__ int    g_deg_in[NMAX];
__device__ float  g_snorm[NMAX];
__device__ float  g_dnorm[NMAX];
__device__ int    g_rowptr[NMAX + 1];
__device__ int    g_cursor[NMAX];
__device__ int    g_partials[128];
__device__ int2   g_edges[EMAX];   // .x = src, .y = bits of 0.9*snorm[src]*dnorm[dst]

// ---------------- graph preprocessing ----------------
__global__ void k_zero_deg(int n) {
    int i = blockIdx.x * blockDim.x + threadIdx.x;
    if (i < n) { g_deg_out[i] = 0; g_deg_in[i] = 0; }
}

__global__ void k_degrees(const int* __restrict__ src, const int* __restrict__ dst, int e) {
    int i = blockIdx.x * blockDim.x + threadIdx.x;
    if (i < e) {
        atomicAdd(&g_deg_out[src[i]], 1);
        atomicAdd(&g_deg_in[dst[i]], 1);
    }
}

__global__ void k_norms_tilesum(int n) {
    int idx = blockIdx.x * 1024 + threadIdx.x;
    int din = 0;
    if (idx < n) {
        int dout = g_deg_out[idx];
        g_snorm[idx] = (dout > 0) ? rsqrtf((float)dout) : 0.f;
        din = g_deg_in[idx];
        g_dnorm[idx] = (din > 0) ? rsqrtf((float)din) : 0.f;
    }
    int v = din;
    #pragma unroll
    for (int o = 16; o; o >>= 1) v += __shfl_down_sync(0xffffffffu, v, o);
    __shared__ int sm[32];
    if ((threadIdx.x & 31) == 0) sm[threadIdx.x >> 5] = v;
    __syncthreads();
    if (threadIdx.x < 32) {
        int s = sm[threadIdx.x];
        #pragma unroll
        for (int o = 16; o; o >>= 1) s += __shfl_down_sync(0xffffffffu, s, o);
        if (threadIdx.x == 0) g_partials[blockIdx.x] = s;
    }
}

__global__ void k_scan_partials(int ntiles) {
    int t = threadIdx.x;
    int v = (t < ntiles) ? g_partials[t] : 0;
    int lane = t & 31, w = t >> 5;
    int x = v;
    #pragma unroll
    for (int o = 1; o < 32; o <<= 1) {
        int y = __shfl_up_sync(0xffffffffu, x, o);
        if (lane >= o) x += y;
    }
    __shared__ int ws[4];
    if (lane == 31) ws[w] = x;
    __syncthreads();
    if (t == 0) {
        int a = 0;
        #pragma unroll
        for (int i = 0; i < 4; i++) { int tmp = ws[i]; ws[i] = a; a += tmp; }
    }
    __syncthreads();
    int excl = x - v + ws[w];
    if (t < ntiles) g_partials[t] = excl;
}

__global__ void k_apply_scan(int n) {
    int tile = blockIdx.x;
    int t = threadIdx.x;
    int idx = tile * 1024 + t;
    int v = (idx < n) ? g_deg_in[idx] : 0;
    int lane = t & 31, w = t >> 5;
    int x = v;
    #pragma unroll
    for (int o = 1; o < 32; o <<= 1) {
        int y = __shfl_up_sync(0xffffffffu, x, o);
        if (lane >= o) x += y;
    }
    __shared__ int ws[32];
    if (lane == 31) ws[w] = x;
    __syncthreads();
    if (t < 32) {
        int y = ws[t];
        #pragma unroll
        for (int o = 1; o < 32; o <<= 1) {
            int z = __shfl_up_sync(0xffffffffu, y, o);
            if (lane >= o) y += z;
        }
        ws[t] = y;
    }
    __syncthreads();
    int winc = (w > 0) ? ws[w - 1] : 0;
    int inc = x + winc + g_partials[tile];
    if (idx < n) {
        g_rowptr[idx + 1] = inc;
        g_cursor[idx] = inc - v;
    }
    if (idx == 0) g_rowptr[0] = 0;
}

__global__ void k_fill(const int* __restrict__ src, const int* __restrict__ dst, int e) {
    int i = blockIdx.x * blockDim.x + threadIdx.x;
    if (i < e) {
        int d = dst[i];
        int s = src[i];
        int p = atomicAdd(&g_cursor[d], 1);
        int2 v;
        v.x = s;
        v.y = __float_as_int(0.9f * g_snorm[s] * g_dnorm[d]);
        g_edges[p] = v;
    }
}

// fp32 features -> fp16 rows (one thread = 8 floats = one uint4 of halves)
__global__ void k_to_half(const float4* __restrict__ in, uint4* __restrict__ out, int nchunks) {
    int i = blockIdx.x * blockDim.x + threadIdx.x;
    if (i < nchunks) {
        float4 x = in[2 * i];
        float4 y = in[2 * i + 1];
        uint4 o;
        o.x = h2_bits(__float22half2_rn(make_float2(x.x, x.y)));
        o.y = h2_bits(__float22half2_rn(make_float2(x.z, x.w)));
        o.z = h2_bits(__float22half2_rn(make_float2(y.x, y.y)));
        o.w = h2_bits(__float22half2_rn(make_float2(y.z, y.w)));
        out[i] = o;
    }
}

// ---------------- APPNP propagation: fp16 rows, 8 lanes/node, grid-stride ----------------
#define ACC8(W, V) { \
    float2 _t0 = __half22float2(bits_h2((V).x)); \
    float2 _t1 = __half22float2(bits_h2((V).y)); \
    float2 _t2 = __half22float2(bits_h2((V).z)); \
    float2 _t3 = __half22float2(bits_h2((V).w)); \
    a0 = fmaf(W, _t0.x, a0); a1 = fmaf(W, _t0.y, a1); \
    a2 = fmaf(W, _t1.x, a2); a3 = fmaf(W, _t1.y, a3); \
    a4 = fmaf(W, _t2.x, a4); a5 = fmaf(W, _t2.y, a5); \
    a6 = fmaf(W, _t3.x, a6); a7 = fmaf(W, _t3.y, a7); }

template<bool OUT32>
__global__ void __launch_bounds__(256, 5) k_prop_h(
        const uint4* __restrict__ fp, const uint4* __restrict__ f0,
        void* __restrict__ fnv, int n) {
    int lane = threadIdx.x & 7;                    // 8 lanes per node
    int node0 = blockIdx.x * 32 + (threadIdx.x >> 3);
    int stride = gridDim.x * 32;

    for (int node = node0; node < n; node += stride) {
        int beg = __ldg(&g_rowptr[node]);
        int end = __ldg(&g_rowptr[node + 1]);

        float a0 = 0.f, a1 = 0.f, a2 = 0.f, a3 = 0.f;
        float a4 = 0.f, a5 = 0.f, a6 = 0.f, a7 = 0.f;

        int e = beg;
        for (; e + 4 <= end; e += 4) {
            int2 e0 = __ldg(&g_edges[e + 0]);
            int2 e1 = __ldg(&g_edges[e + 1]);
            int2 e2 = __ldg(&g_edges[e + 2]);
            int2 e3 = __ldg(&g_edges[e + 3]);
            uint4 v0 = __ldg(&fp[(size_t)e0.x * 8 + lane]);
            uint4 v1 = __ldg(&fp[(size_t)e1.x * 8 + lane]);
            uint4 v2 = __ldg(&fp[(size_t)e2.x * 8 + lane]);
            uint4 v3 = __ldg(&fp[(size_t)e3.x * 8 + lane]);
            float w0 = __int_as_float(e0.y), w1 = __int_as_float(e1.y);
            float w2 = __int_as_float(e2.y), w3 = __int_as_float(e3.y);
            ACC8(w0, v0); ACC8(w1, v1); ACC8(w2, v2); ACC8(w3, v3);
        }
        if (e + 2 <= end) {
            int2 e0 = __ldg(&g_edges[e + 0]);
            int2 e1 = __ldg(&g_edges[e + 1]);
            uint4 v0 = __ldg(&fp[(size_t)e0.x * 8 + lane]);
            uint4 v1 = __ldg(&fp[(size_t)e1.x * 8 + lane]);
            float w0 = __int_as_float(e0.y), w1 = __int_as_float(e1.y);
            ACC8(w0, v0); ACC8(w1, v1);
            e += 2;
        }
        if (e < end) {
            int2 ev = __ldg(&g_edges[e]);
            uint4 v = __ldg(&fp[(size_t)ev.x * 8 + lane]);
            float w = __int_as_float(ev.y);
            ACC8(w, v);
        }

        // + 0.1 * f0
        {
            uint4 b = __ldg(&f0[(size_t)node * 8 + lane]);
            float2 t0 = __half22float2(bits_h2(b.x));
            float2 t1 = __half22float2(bits_h2(b.y));
            float2 t2 = __half22float2(bits_h2(b.z));
            float2 t3 = __half22float2(bits_h2(b.w));
            a0 = fmaf(0.1f, t0.x, a0); a1 = fmaf(0.1f, t0.y, a1);
            a2 = fmaf(0.1f, t1.x, a2); a3 = fmaf(0.1f, t1.y, a3);
            a4 = fmaf(0.1f, t2.x, a4); a5 = fmaf(0.1f, t2.y, a5);
            a6 = fmaf(0.1f, t3.x, a6); a7 = fmaf(0.1f, t3.y, a7);
        }

        if (OUT32) {
            float4* out = (float4*)fnv;
            out[(size_t)node * 16 + lane * 2 + 0] = make_float4(a0, a1, a2, a3);
            out[(size_t)node * 16 + lane * 2 + 1] = make_float4(a4, a5, a6, a7);
        } else {
            uint4 o;
            o.x = h2_bits(__float22half2_rn(make_float2(a0, a1)));
            o.y = h2_bits(__float22half2_rn(make_float2(a2, a3)));
            o.z = h2_bits(__float22half2_rn(make_float2(a4, a5)));
            o.w = h2_bits(__float22half2_rn(make_float2(a6, a7)));
            ((uint4*)fnv)[(size_t)node * 8 + lane] = o;
        }
    }
}

// ---------------- fused tf32 MLP (unchanged from R6) ----------------
__device__ __forceinline__ uint32_t f2tf32(float v) {
    uint32_t u;
    asm("cvt.rna.tf32.f32 %0, %1;" : "=r"(u) : "f"(v));
    return u;
}

template<int K, int NF>
__device__ __forceinline__ void mma_stage(
        const uint32_t* __restrict__ sA, const uint32_t* __restrict__ sW,
        int wm, int wn, int g, int tg, float (&acc)[2][8][4]) {
    #pragma unroll
    for (int kk = 0; kk < K; kk += 8) {
        uint32_t afr[2][4];
        #pragma unroll
        for (int mf = 0; mf < 2; mf++) {
            int mr = wm * 32 + mf * 16 + g;
            afr[mf][0] = sA[(kk + tg    ) * SAPAD + mr    ];
            afr[mf][1] = sA[(kk + tg    ) * SAPAD + mr + 8];
            afr[mf][2] = sA[(kk + tg + 4) * SAPAD + mr    ];
            afr[mf][3] = sA[(kk + tg + 4) * SAPAD + mr + 8];
        }
        #pragma unroll
        for (int nf = 0; nf < NF; nf++) {
            int nr = wn * NF * 8 + nf * 8 + g;
            uint32_t b0 = sW[(kk + tg    ) * SAPAD + nr];
            uint32_t b1 = sW[(kk + tg + 4) * SAPAD + nr];
            #pragma unroll
            for (int mf = 0; mf < 2; mf++) {
                asm volatile(
                    "mma.sync.aligned.m16n8k8.row.col.f32.tf32.tf32.f32 "
                    "{%0,%1,%2,%3}, {%4,%5,%6,%7}, {%8,%9}, {%0,%1,%2,%3};"
                    : "+f"(acc[mf][nf][0]), "+f"(acc[mf][nf][1]),
                      "+f"(acc[mf][nf][2]), "+f"(acc[mf][nf][3])
                    : "r"(afr[mf][0]), "r"(afr[mf][1]), "r"(afr[mf][2]), "r"(afr[mf][3]),
                      "r"(b0), "r"(b1));
            }
        }
    }
}

__device__ __forceinline__ void zero_acc(float (&acc)[2][8][4]) {
    #pragma unroll
    for (int i = 0; i < 2; i++)
        #pragma unroll
        for (int j = 0; j < 8; j++)
            #pragma unroll
            for (int r = 0; r < 4; r++) acc[i][j][r] = 0.f;
}

template<int NF, bool RELU, bool TO_SA, bool TO_GM>
__device__ __forceinline__ void store_acts(
        float (&acc)[2][8][4], const float* __restrict__ bias,
        uint32_t* __restrict__ sA, int wm, int wn, int g, int tg,
        float* __restrict__ gm_out, int gm_cols, int col_limit,
        int rowBase, int M) {
    #pragma unroll
    for (int mf = 0; mf < 2; mf++) {
        int r0 = wm * 32 + mf * 16 + g, r1 = r0 + 8;
        #pragma unroll
        for (int nf = 0; nf < NF; nf++) {
            int c0 = wn * NF * 8 + nf * 8 + tg * 2, c1 = c0 + 1;
            float bv0 = (c0 < col_limit) ? bias[c0] : 0.f;
            float bv1 = (c1 < col_limit) ? bias[c1] : 0.f;
            float v00 = acc[mf][nf][0] + bv0;
            float v01 = acc[mf][nf][1] + bv1;
            float v10 = acc[mf][nf][2] + bv0;
            float v11 = acc[mf][nf][3] + bv1;
            if (RELU) {
                v00 = fmaxf(v00, 0.f); v01 = fmaxf(v01, 0.f);
                v10 = fmaxf(v10, 0.f); v11 = fmaxf(v11, 0.f);
            }
            if (TO_SA) {
                sA[c0 * SAPAD + r0] = f2tf32(v00);
                sA[c1 * SAPAD + r0] = f2tf32(v01);
                sA[c0 * SAPAD + r1] = f2tf32(v10);
                sA[c1 * SAPAD + r1] = f2tf32(v11);
            }
            if (TO_GM) {
                int gr0 = rowBase + r0, gr1 = rowBase + r1;
                if (gr0 < M) {
                    if (c0 < col_limit) gm_out[(size_t)gr0 * gm_cols + c0] = v00;
                    if (c1 < col_limit) gm_out[(size_t)gr0 * gm_cols + c1] = v01;
                }
                if (gr1 < M) {
                    if (c0 < col_limit) gm_out[(size_t)gr1 * gm_cols + c0] = v10;
                    if (c1 < col_limit) gm_out[(size_t)gr1 * gm_cols + c1] = v11;
                }
            }
        }
    }
}

__global__ void __launch_bounds__(256) k_mlp(
        const float* __restrict__ X,
        const float* __restrict__ W1,  const float* __restrict__ b1,
        const float* __restrict__ W2,  const float* __restrict__ b2,
        const float* __restrict__ Wh1, const float* __restrict__ bh1,
        const float* __restrict__ Wh2, const float* __restrict__ bh2,
        float* __restrict__ hlast, float* __restrict__ out, int M) {
    extern __shared__ uint32_t sh[];
    uint32_t* sA = sh;
    uint32_t* sW = sh + 128 * SAPAD;

    int tid = threadIdx.x;
    int wid = tid >> 5, lane = tid & 31;
    int g = lane >> 2, tg = lane & 3;
    int wm = wid & 3, wn = wid >> 2;
    int rowBase = blockIdx.x * 128;

    #pragma unroll
    for (int i = tid; i < 128 * 16; i += 256) {
        int m = i / 16, kq = i % 16;
        float4 v = make_float4(0.f, 0.f, 0.f, 0.f);
        int gm = rowBase + m;
        if (gm < M) v = *reinterpret_cast<const float4*>(&X[(size_t)gm * 64 + kq * 4]);
        sA[(kq * 4 + 0) * SAPAD + m] = f2tf32(v.x);
        sA[(kq * 4 + 1) * SAPAD + m] = f2tf32(v.y);
        sA[(kq * 4 + 2) * SAPAD + m] = f2tf32(v.z);
        sA[(kq * 4 + 3) * SAPAD + m] = f2tf32(v.w);
    }
    #pragma unroll
    for (int i = tid; i < 64 * 32; i += 256) {
        int k = i / 32, nq = i % 32;
        float4 v = *reinterpret_cast<const float4*>(&W1[(size_t)k * 128 + nq * 4]);
        sW[k * SAPAD + nq * 4 + 0] = f2tf32(v.x);
        sW[k * SAPAD + nq * 4 + 1] = f2tf32(v.y);
        sW[k * SAPAD + nq * 4 + 2] = f2tf32(v.z);
        sW[k * SAPAD + nq * 4 + 3] = f2tf32(v.w);
    }
    __syncthreads();

    float acc[2][8][4];

    zero_acc(acc);
    mma_stage<64, 8>(sA, sW, wm, wn, g, tg, acc);
    __syncthreads();
    store_acts<8, true, true, false>(acc, b1, sA, wm, wn, g, tg, nullptr, 0, 128, rowBase, M);
    #pragma unroll
    for (int i = tid; i < 128 * 32; i += 256) {
        int k = i / 32, nq = i % 32;
        float4 v = *reinterpret_cast<const float4*>(&W2[(size_t)k * 128 + nq * 4]);
        sW[k * SAPAD + nq * 4 + 0] = f2tf32(v.x);
        sW[k * SAPAD + nq * 4 + 1] = f2tf32(v.y);
        sW[k * SAPAD + nq * 4 + 2] = f2tf32(v.z);
        sW[k * SAPAD + nq * 4 + 3] = f2tf32(v.w);
    }
    __syncthreads();

    zero_acc(acc);
    mma_stage<128, 8>(sA, sW, wm, wn, g, tg, acc);
    __syncthreads();
    store_acts<8, false, true, true>(acc, b2, sA, wm, wn, g, tg, hlast, 128, 128, rowBase, M);
    #pragma unroll
    for (int i = tid; i < 128 * 16; i += 256) {
        int k = i / 16, nq = i % 16;
        float4 v = *reinterpret_cast<const float4*>(&Wh1[(size_t)k * 64 + nq * 4]);
        sW[k * SAPAD + nq * 4 + 0] = f2tf32(v.x);
        sW[k * SAPAD + nq * 4 + 1] = f2tf32(v.y);
        sW[k * SAPAD + nq * 4 + 2] = f2tf32(v.z);
        sW[k * SAPAD + nq * 4 + 3] = f2tf32(v.w);
    }
    __syncthreads();

    zero_acc(acc);
    mma_stage<128, 4>(sA, sW, wm, wn, g, tg, acc);
    __syncthreads();
    store_acts<4, true, true, false>(acc, bh1, sA, wm, wn, g, tg, nullptr, 0, 64, rowBase, M);
    #pragma unroll
    for (int i = tid; i < 64 * 64; i += 256) {
        int k = i / 64, j = i % 64;
        float v = (j < 40) ? Wh2[(size_t)k * 40 + j] : 0.f;
        sW[k * SAPAD + j] = f2tf32(v);
    }
    __syncthreads();

    zero_acc(acc);
    mma_stage<64, 4>(sA, sW, wm, wn, g, tg, acc);
    __syncthreads();
    store_acts<4, false, false, true>(acc, bh2, nullptr, wm, wn, g, tg, out, 40, 40, rowBase, M);
}

// ---------------- launch ----------------
extern "C" void kernel_launch(void* const* d_in, const int* in_sizes, int n_in,
                              void* d_out, int out_size) {
    const float* input_feat = (const float*)d_in[0];
    const int*   src = (const int*)d_in[1];
    const int*   dst = (const int*)d_in[2];
    const float* W1  = (const float*)d_in[3];
    const float* b1  = (const float*)d_in[4];
    const float* W2  = (const float*)d_in[5];
    const float* b2  = (const float*)d_in[6];
    const float* Wh1 = (const float*)d_in[7];
    const float* bh1 = (const float*)d_in[8];
    const float* Wh2 = (const float*)d_in[9];
    const float* bh2 = (const float*)d_in[10];

    int n = in_sizes[0] / 64;
    int e = in_sizes[1];
    if (n > NMAX) n = NMAX;
    if (e > EMAX) e = EMAX;

    float* outp = (float*)d_out;

    uint4 *h0, *hA, *hB, *hC;
    float4 *f32out, *hl_scratch;
    cudaGetSymbolAddress((void**)&h0, g_h0);
    cudaGetSymbolAddress((void**)&hA, g_hA);
    cudaGetSymbolAddress((void**)&hB, g_hB);
    cudaGetSymbolAddress((void**)&hC, g_hC);
    cudaGetSymbolAddress((void**)&f32out, g_f32out);
    cudaGetSymbolAddress((void**)&hl_scratch, g_hlast_scratch);

    float* hlast = (out_size >= n * 168) ? (outp + (size_t)n * 40) : (float*)hl_scratch;

    int nb = (n + 255) / 256;
    int eb = (e + 255) / 256;
    int ntiles = (n + 1023) / 1024;

    k_zero_deg<<<nb, 256>>>(n);
    k_degrees<<<eb, 256>>>(src, dst, e);
    k_norms_tilesum<<<ntiles, 1024>>>(n);
    k_scan_partials<<<1, 128>>>(ntiles);
    k_apply_scan<<<ntiles, 1024>>>(n);
    k_fill<<<eb, 256>>>(src, dst, e);

    // fp32 input -> fp16 rows
    int nch = n * 8;
    k_to_half<<<(nch + 255) / 256, 256>>>((const float4*)input_feat, h0, nch);

    // grid-stride persistent-shape prop
    int dev = 0, smCount = 148;
    cudaGetDevice(&dev);
    cudaDeviceGetAttribute(&smCount, cudaDevAttrMultiProcessorCount, dev);
    int pbMax = (n + 31) / 32;
    int pb = smCount * 5;
    if (pb > pbMax) pb = pbMax;

    // gnn1: f0 = h0; ping-pong hA/hB, ends in hB
    const uint4* f = h0;
    for (int s = 0; s < 10; s++) {
        uint4* o = (s % 2 == 0) ? hA : hB;
        k_prop_h<false><<<pb, 256>>>(f, h0, o, n);
        f = o;
    }
    // gnn2: f0 = hB; steps 0..8 ping-pong hA/hC; final step writes fp32
    const uint4* f02 = f;   // hB
    for (int s = 0; s < 9; s++) {
        uint4* o = (s % 2 == 0) ? hA : hC;
        k_prop_h<false><<<pb, 256>>>(f, f02, o, n);
        f = o;
    }
    k_prop_h<true><<<pb, 256>>>(f, f02, f32out, n);   // step 20 -> fp32 MLP input

    // fused MLP (fp32 input, unchanged)
    const int MLP_SMEM = 2 * 128 * SAPAD * 4;
    cudaFuncSetAttribute(k_mlp, cudaFuncAttributeMaxDynamicSharedMemorySize, MLP_SMEM);
    int gridM = (n + 127) / 128;
    k_mlp<<<gridM, 256, MLP_SMEM>>>((const float*)f32out, W1, b1, W2, b2,
                                    Wh1, bh1, Wh2, bh2, hlast, outp, n);
}